// round 8
// baseline (speedup 1.0000x reference)
#include <cuda_runtime.h>
#include <math.h>

// Problem constants
#define BB 64      // batch
#define TT 256     // time steps
#define HH 512     // hidden
#define NG 3584    // 7*H gate width
#define KK 512     // per-half K (x part / h part each 512)

typedef unsigned long long u64;
typedef unsigned int u32;

// ---------------- tf32 mma helpers ----------------
__device__ __forceinline__ u32 f2tf32(float f) {
    u32 u; asm("cvt.rna.tf32.f32 %0, %1;" : "=r"(u) : "f"(f)); return u;
}
__device__ __forceinline__ void mma_tf32(float &c0, float &c1, float &c2, float &c3,
                                         u32 a0, u32 a1, u32 a2, u32 a3,
                                         u32 b0, u32 b1) {
    asm("mma.sync.aligned.m16n8k8.row.col.f32.tf32.tf32.f32 "
        "{%0,%1,%2,%3},{%4,%5,%6,%7},{%8,%9},{%0,%1,%2,%3};"
        : "+f"(c0), "+f"(c1), "+f"(c2), "+f"(c3)
        : "r"(a0), "r"(a1), "r"(a2), "r"(a3), "r"(b0), "r"(b1));
}

// ---------------- scratch (no allocations allowed) ----------------
// GX layout: [t][b][n], n = j*512 + c  (x-part pre-activations + bias)
__device__ float g_gx[(long long)BB * TT * NG];   // ~224MB
#define NBLK 128
// flag-array barrier state: one 128B-spaced slot per CTA + one generation word
__device__ u32 g_flags[NBLK * 32];   // zero-init; monotonic across replays
__device__ u32 g_gen = 0;

// ---------------- Phase 1: GX = X @ W[0:512] + b  via tf32 mma -------------
#define TBM 128
#define TBN 128
#define TBK 16
#define ASTRIDE 20      // As [m][16+4]
#define BSTRIDE 136     // Bs [k][128+8]
#define NIT (KK / TBK)  // 32

__global__ __launch_bounds__(256, 1) void gemm_gx_tf32(
    const float* __restrict__ X,   // [B*T, 512]
    const float* __restrict__ W,   // [1024, 3584]
    const float* __restrict__ bias,// [3584]
    float* __restrict__ GX)        // [T][B][3584]
{
    __shared__ u32 As[TBM * ASTRIDE];
    __shared__ u32 Bs[TBK * BSTRIDE];

    const int tid = threadIdx.x;
    const int bm = blockIdx.y * TBM;
    const int bn = blockIdx.x * TBN;
    const int w = tid >> 5, l = tid & 31;
    const int wr = w >> 2, wc = w & 3;
    const int m0w = wr * 64, n0w = wc * 32;
    const int g = l >> 2, tk = l & 3;

    const int arow = tid >> 1;
    const int acol = (tid & 1) * 8;
    const int brow = tid >> 4;
    const int bcol = (tid & 15) * 4;

    const float* Aptr = X + (long long)(bm + arow) * KK + acol;
    const float* Bptr = W + (long long)brow * NG + bn + bcol;

    float4 ra0 = *(const float4*)(Aptr);
    float4 ra1 = *(const float4*)(Aptr + 4);
    float4 rb0 = *(const float4*)(Bptr);
    float4 rb1 = *(const float4*)(Bptr + 64);

    float acc[4][4][4];
#pragma unroll
    for (int mi = 0; mi < 4; mi++)
#pragma unroll
        for (int ni = 0; ni < 4; ni++)
#pragma unroll
            for (int q = 0; q < 4; q++) acc[mi][ni][q] = 0.f;

    for (int it = 0; it < NIT; it++) {
        u32* as = &As[arow * ASTRIDE + acol];
        as[0] = f2tf32(ra0.x); as[1] = f2tf32(ra0.y);
        as[2] = f2tf32(ra0.z); as[3] = f2tf32(ra0.w);
        as[4] = f2tf32(ra1.x); as[5] = f2tf32(ra1.y);
        as[6] = f2tf32(ra1.z); as[7] = f2tf32(ra1.w);
        u32* bs = &Bs[brow * BSTRIDE + bcol];
        bs[0] = f2tf32(rb0.x); bs[1] = f2tf32(rb0.y);
        bs[2] = f2tf32(rb0.z); bs[3] = f2tf32(rb0.w);
        bs[64] = f2tf32(rb1.x); bs[65] = f2tf32(rb1.y);
        bs[66] = f2tf32(rb1.z); bs[67] = f2tf32(rb1.w);
        __syncthreads();

        if (it < NIT - 1) {
            const float* An = Aptr + (it + 1) * TBK;
            const float* Bn = Bptr + (long long)(it + 1) * TBK * NG;
            ra0 = *(const float4*)(An);
            ra1 = *(const float4*)(An + 4);
            rb0 = *(const float4*)(Bn);
            rb1 = *(const float4*)(Bn + 64);
        }

#pragma unroll
        for (int kc = 0; kc < 2; kc++) {
            const int kb = kc * 8;
            u32 af[4][4];
#pragma unroll
            for (int mi = 0; mi < 4; mi++) {
                const u32* ap0 = &As[(m0w + mi * 16 + g) * ASTRIDE + kb + tk];
                const u32* ap1 = &As[(m0w + mi * 16 + g + 8) * ASTRIDE + kb + tk];
                af[mi][0] = ap0[0];
                af[mi][1] = ap1[0];
                af[mi][2] = ap0[4];
                af[mi][3] = ap1[4];
            }
            u32 bf[4][2];
#pragma unroll
            for (int ni = 0; ni < 4; ni++) {
                const u32* bp = &Bs[(kb + tk) * BSTRIDE + n0w + ni * 8 + g];
                bf[ni][0] = bp[0];
                bf[ni][1] = bp[4 * BSTRIDE];
            }
#pragma unroll
            for (int mi = 0; mi < 4; mi++)
#pragma unroll
                for (int ni = 0; ni < 4; ni++)
                    mma_tf32(acc[mi][ni][0], acc[mi][ni][1], acc[mi][ni][2], acc[mi][ni][3],
                             af[mi][0], af[mi][1], af[mi][2], af[mi][3],
                             bf[ni][0], bf[ni][1]);
        }
        __syncthreads();
    }

#pragma unroll
    for (int ni = 0; ni < 4; ni++) {
        const int n = bn + n0w + ni * 8 + tk * 2;
        const float2 bv = *(const float2*)&bias[n];
#pragma unroll
        for (int mi = 0; mi < 4; mi++) {
            const int mA = bm + m0w + mi * 16 + g;
            const int mB = mA + 8;
            const int bA = mA >> 8, tA = mA & 255;
            const int bA2 = mB >> 8, tB = mB & 255;
            float2 o0 = make_float2(acc[mi][ni][0] + bv.x, acc[mi][ni][1] + bv.y);
            float2 o1 = make_float2(acc[mi][ni][2] + bv.x, acc[mi][ni][3] + bv.y);
            *(float2*)&GX[((long long)tA * BB + bA) * NG + n] = o0;
            *(float2*)&GX[((long long)tB * BB + bA2) * NG + n] = o1;
        }
    }
}

// ---------------- Phase 2: persistent scan with tf32 mma ----------------
#define HS_STRIDE 516
#define WS_U32 (4 * 64 * 64)        // 16384
#define HS_U32 (BB * HS_STRIDE)     // 33024
#define GH_STRIDE 34
#define GH_F32 (BB * GH_STRIDE)     // 2176
#define SMEM_BYTES ((WS_U32 + HS_U32 + GH_F32) * 4)

// Flag-array grid barrier: no atomics, no per-address serialization.
// Each CTA releases its own flag = tgt; CTA 0's warp 0 gathers all 128 flags,
// then releases g_gen = tgt; all other CTAs acquire-poll g_gen.
// tgt is monotonic (base + t + 1) where base = flag value at kernel entry,
// so graph replays need no reset and there is no reset race.
__device__ __forceinline__ void grid_barrier(u32 tgt) {
    __syncthreads();
    const int tid = threadIdx.x;
    if (blockIdx.x == 0) {
        // publish own arrival, then gather everyone's
        if (tid == 0) {
            asm volatile("st.release.gpu.u32 [%0], %1;"
                         :: "l"(&g_flags[0]), "r"(tgt) : "memory");
        }
        if (tid < 32) {
            const u32* f0 = &g_flags[(tid * 4 + 0) * 32];
            const u32* f1 = &g_flags[(tid * 4 + 1) * 32];
            const u32* f2 = &g_flags[(tid * 4 + 2) * 32];
            const u32* f3 = &g_flags[(tid * 4 + 3) * 32];
            bool done;
            do {
                u32 v0, v1, v2, v3;
                asm volatile("ld.acquire.gpu.u32 %0, [%1];" : "=r"(v0) : "l"(f0) : "memory");
                asm volatile("ld.acquire.gpu.u32 %0, [%1];" : "=r"(v1) : "l"(f1) : "memory");
                asm volatile("ld.acquire.gpu.u32 %0, [%1];" : "=r"(v2) : "l"(f2) : "memory");
                asm volatile("ld.acquire.gpu.u32 %0, [%1];" : "=r"(v3) : "l"(f3) : "memory");
                done = ((int)(v0 - tgt) >= 0) & ((int)(v1 - tgt) >= 0) &
                       ((int)(v2 - tgt) >= 0) & ((int)(v3 - tgt) >= 0);
            } while (!__all_sync(0xffffffffu, done));
            if (tid == 0) {
                asm volatile("st.release.gpu.u32 [%0], %1;"
                             :: "l"(&g_gen), "r"(tgt) : "memory");
            }
        }
    } else {
        if (tid == 0) {
            asm volatile("st.release.gpu.u32 [%0], %1;"
                         :: "l"(&g_flags[blockIdx.x * 32]), "r"(tgt) : "memory");
            u32 cur;
            do {
                asm volatile("ld.acquire.gpu.u32 %0, [%1];"
                             : "=r"(cur) : "l"(&g_gen) : "memory");
            } while ((int)(cur - tgt) < 0);
        }
    }
    __syncthreads();
}

__device__ __forceinline__ float sigmoidf_(float x) {
    return 1.f / (1.f + expf(-x));
}
__device__ __forceinline__ float softplusf_(float x) {
    return fmaxf(x, 0.f) + log1pf(expf(-fabsf(x)));
}

__global__ __launch_bounds__(512, 1) void scan_kernel(
    const float* __restrict__ GX,    // [T][B][3584]
    const float* __restrict__ dtime, // [B,T]
    const float* __restrict__ W,     // [1024, 3584]
    float* out)                      // h_ts[B,T,H] then decay[B,T,4,H]
{
    extern __shared__ u32 smem_u[];
    u32* Ws = smem_u;                       // [4][64][64]
    u32* hs = smem_u + WS_U32;              // [64][516]
    float* gh = (float*)(smem_u + WS_U32 + HS_U32);  // [64][34]

    const int tid = threadIdx.x;
    const int blk = blockIdx.x;
    const int c0 = blk * 4;

    const int w = tid >> 5;
    const int l = tid & 31;
    const int mt = w & 3;
    const int nt = w >> 2;
    const int m0 = mt * 16;
    const int g = l >> 2;
    const int tk = l & 3;

    const int r = tid & 255;
    const int b = r >> 2;
    const int cc = r & 3;
    const int c = c0 + cc;

    // barrier base for this launch (flags are monotonic across graph replays;
    // all flags are equal at entry because the previous launch fully drained)
    u32 bar_base;
    asm volatile("ld.relaxed.gpu.u32 %0, [%1];"
                 : "=r"(bar_base) : "l"(&g_flags[blk * 32]) : "memory");

    // one-time init: W_h fragments (tf32, lane order) + zero gh
    for (int i = tid; i < WS_U32; i += 512) {
        int slot = i & 1;
        int l2 = (i >> 1) & 31;
        int ks = (i >> 6) & 63;
        int nt2 = i >> 12;
        int k = ks * 8 + (l2 & 3) + slot * 4;
        int j = l2 >> 2;
        float v = 0.f;
        if (j < 7) v = W[(long long)(KK + k) * NG + j * HH + c0 + nt2];
        Ws[i] = f2tf32(v);
    }
    for (int i = tid; i < GH_F32; i += 512) gh[i] = 0.f;
    __syncthreads();

    float cf_r = 0.f;
    float cb_r = 0.f;

    const u32* hA0 = hs + (m0 + g) * HS_STRIDE + tk;
    const u32* hA1 = hs + (m0 + g + 8) * HS_STRIDE + tk;
    const u32* wB  = Ws + nt * 64 * 64 + l * 2;
    const long long DEC0 = (long long)BB * TT * HH;

    // prefetch step-0 gate inputs
    float x0, x1, x2, x3, x4, x5, x6, dt;
    if (tid < 256) {
        const float* gx = GX + (long long)b * NG + c;
        x0 = gx[0 * HH];
        x1 = gx[1 * HH];
        x2 = gx[2 * HH];
        x3 = gx[3 * HH];
        x4 = gx[4 * HH];
        x5 = gx[5 * HH];
        x6 = gx[6 * HH];
        dt = dtime[b * TT];
    }

    for (int t = 0; t < TT; t++) {
        if (t > 0) {
            // stage h_{t-1} -> SMEM (tf32)
#pragma unroll
            for (int i = 0; i < 16; i++) {
                int lin = i * 512 + tid;
                int bb = lin >> 7;
                int q = lin & 127;
                float4 v = *(const float4*)&out[((long long)bb * TT + (t - 1)) * HH + q * 4];
                uint4 u;
                u.x = f2tf32(v.x);
                u.y = f2tf32(v.y);
                u.z = f2tf32(v.z);
                u.w = f2tf32(v.w);
                *(uint4*)&hs[bb * HS_STRIDE + q * 4] = u;
            }
            __syncthreads();

            float acc0 = 0.f, acc1 = 0.f, acc2 = 0.f, acc3 = 0.f;
#pragma unroll 8
            for (int ks = 0; ks < 64; ks++) {
                u32 a0 = hA0[ks * 8];
                u32 a2 = hA0[ks * 8 + 4];
                u32 a1 = hA1[ks * 8];
                u32 a3 = hA1[ks * 8 + 4];
                uint2 bfr = *(const uint2*)(wB + ks * 64);
                mma_tf32(acc0, acc1, acc2, acc3, a0, a1, a2, a3, bfr.x, bfr.y);
            }

            const int col = nt * 8 + tk * 2;
            *(float2*)&gh[(m0 + g) * GH_STRIDE + col] = make_float2(acc0, acc1);
            *(float2*)&gh[(m0 + g + 8) * GH_STRIDE + col] = make_float2(acc2, acc3);
            __syncthreads();
        }

        if (tid < 256) {
            const float* ghr = &gh[b * GH_STRIDE + cc * 8];
            const float g0 = x0 + ghr[0];
            const float g1 = x1 + ghr[1];
            const float g2 = x2 + ghr[2];
            const float g3 = x3 + ghr[3];
            const float g4 = x4 + ghr[4];
            const float g5 = x5 + ghr[5];
            const float g6 = x6 + ghr[6];

            const float gate_i  = sigmoidf_(g0);
            const float gate_f  = sigmoidf_(g1);
            const float gate_o  = sigmoidf_(g2);
            const float gate_ib = sigmoidf_(g3);
            const float gate_fb = sigmoidf_(g4);
            const float gate_d  = softplusf_(g5);
            const float z       = tanhf(g6);

            const float c_t  = gate_f  * cf_r + gate_i  * z;
            const float cb_t = gate_fb * cb_r + gate_ib * z;
            const float cfn  = cb_t + (c_t - cb_t) * expf(-gate_d * dt);
            const float h_t  = gate_o * tanhf(cfn);

            cf_r = cfn;
            cb_r = cb_t;

            out[((long long)b * TT + t) * HH + c] = h_t;
            float* dec = out + DEC0 + ((long long)(b * TT + t) * 4) * HH + c;
            dec[0 * HH] = c_t;
            dec[1 * HH] = cb_t;
            dec[2 * HH] = gate_d;
            dec[3 * HH] = gate_o;

            // prefetch next step's gate inputs; latency hides in the barrier
            if (t + 1 < TT) {
                const float* gx = GX + ((long long)(t + 1) * BB + b) * NG + c;
                x0 = gx[0 * HH];
                x1 = gx[1 * HH];
                x2 = gx[2 * HH];
                x3 = gx[3 * HH];
                x4 = gx[4 * HH];
                x5 = gx[5 * HH];
                x6 = gx[6 * HH];
                dt = dtime[b * TT + t + 1];
            }
        }

        if (t + 1 < TT) grid_barrier(bar_base + (u32)t + 1u);
    }
}

// ---------------- launch ----------------
extern "C" void kernel_launch(void* const* d_in, const int* in_sizes, int n_in,
                              void* d_out, int out_size) {
    (void)in_sizes; (void)n_in; (void)out_size;
    const float* X     = (const float*)d_in[0];  // seq_type_embed [B,T,H]
    const float* dtime = (const float*)d_in[1];  // [B,T]
    const float* W     = (const float*)d_in[2];  // [2H, 7H]
    const float* bias  = (const float*)d_in[3];  // [7H]
    float* out = (float*)d_out;

    float* GX;
    cudaGetSymbolAddress((void**)&GX, g_gx);

    // Phase 1: tf32 mma GEMM for x-part pre-activations
    dim3 grid1(NG / TBN, (BB * TT) / TBM);   // (28, 128)
    gemm_gx_tf32<<<grid1, 256>>>(X, W, bias, GX);

    // Phase 2: one persistent kernel for the whole scan
    cudaFuncSetAttribute(scan_kernel, cudaFuncAttributeMaxDynamicSharedMemorySize,
                         SMEM_BYTES);
    scan_kernel<<<NBLK, 512, SMEM_BYTES>>>(GX, dtime, W, out);
}

// round 10
// speedup vs baseline: 1.1983x; 1.1983x over previous
#include <cuda_runtime.h>
#include <math.h>

// Problem constants
#define BB 64      // batch
#define TT 256     // time steps
#define HH 512     // hidden
#define NG 3584    // 7*H gate width
#define KK 512     // per-half K (x part / h part each 512)

typedef unsigned long long u64;
typedef unsigned int u32;

// ---------------- tf32 mma helpers ----------------
__device__ __forceinline__ u32 f2tf32(float f) {
    u32 u; asm("cvt.rna.tf32.f32 %0, %1;" : "=r"(u) : "f"(f)); return u;
}
__device__ __forceinline__ void mma_tf32(float &c0, float &c1, float &c2, float &c3,
                                         u32 a0, u32 a1, u32 a2, u32 a3,
                                         u32 b0, u32 b1) {
    asm("mma.sync.aligned.m16n8k8.row.col.f32.tf32.tf32.f32 "
        "{%0,%1,%2,%3},{%4,%5,%6,%7},{%8,%9},{%0,%1,%2,%3};"
        : "+f"(c0), "+f"(c1), "+f"(c2), "+f"(c3)
        : "r"(a0), "r"(a1), "r"(a2), "r"(a3), "r"(b0), "r"(b1));
}

// ---------------- scratch (no allocations allowed) ----------------
// GX layout: [t][b][n], n = j*512 + c  (x-part pre-activations + bias)
__device__ float g_gx[(long long)BB * TT * NG];   // ~224MB
__device__ u32 g_bar_count = 0;
__device__ u32 g_bar_gen = 0;

// ---------------- Phase 1: GX = X @ W[0:512] + b  via tf32 mma -------------
#define TBM 128
#define TBN 128
#define TBK 16
#define ASTRIDE 20      // As [m][16+4]
#define BSTRIDE 136     // Bs [k][128+8]
#define NIT (KK / TBK)  // 32

__global__ __launch_bounds__(256, 1) void gemm_gx_tf32(
    const float* __restrict__ X,   // [B*T, 512]
    const float* __restrict__ W,   // [1024, 3584]
    const float* __restrict__ bias,// [3584]
    float* __restrict__ GX)        // [T][B][3584]
{
    __shared__ u32 As[TBM * ASTRIDE];
    __shared__ u32 Bs[TBK * BSTRIDE];

    const int tid = threadIdx.x;
    const int bm = blockIdx.y * TBM;
    const int bn = blockIdx.x * TBN;
    const int w = tid >> 5, l = tid & 31;
    const int wr = w >> 2, wc = w & 3;
    const int m0w = wr * 64, n0w = wc * 32;
    const int g = l >> 2, tk = l & 3;

    const int arow = tid >> 1;
    const int acol = (tid & 1) * 8;
    const int brow = tid >> 4;
    const int bcol = (tid & 15) * 4;

    const float* Aptr = X + (long long)(bm + arow) * KK + acol;
    const float* Bptr = W + (long long)brow * NG + bn + bcol;

    float4 ra0 = *(const float4*)(Aptr);
    float4 ra1 = *(const float4*)(Aptr + 4);
    float4 rb0 = *(const float4*)(Bptr);
    float4 rb1 = *(const float4*)(Bptr + 64);

    float acc[4][4][4];
#pragma unroll
    for (int mi = 0; mi < 4; mi++)
#pragma unroll
        for (int ni = 0; ni < 4; ni++)
#pragma unroll
            for (int q = 0; q < 4; q++) acc[mi][ni][q] = 0.f;

    for (int it = 0; it < NIT; it++) {
        u32* as = &As[arow * ASTRIDE + acol];
        as[0] = f2tf32(ra0.x); as[1] = f2tf32(ra0.y);
        as[2] = f2tf32(ra0.z); as[3] = f2tf32(ra0.w);
        as[4] = f2tf32(ra1.x); as[5] = f2tf32(ra1.y);
        as[6] = f2tf32(ra1.z); as[7] = f2tf32(ra1.w);
        u32* bs = &Bs[brow * BSTRIDE + bcol];
        bs[0] = f2tf32(rb0.x); bs[1] = f2tf32(rb0.y);
        bs[2] = f2tf32(rb0.z); bs[3] = f2tf32(rb0.w);
        bs[64] = f2tf32(rb1.x); bs[65] = f2tf32(rb1.y);
        bs[66] = f2tf32(rb1.z); bs[67] = f2tf32(rb1.w);
        __syncthreads();

        if (it < NIT - 1) {
            const float* An = Aptr + (it + 1) * TBK;
            const float* Bn = Bptr + (long long)(it + 1) * TBK * NG;
            ra0 = *(const float4*)(An);
            ra1 = *(const float4*)(An + 4);
            rb0 = *(const float4*)(Bn);
            rb1 = *(const float4*)(Bn + 64);
        }

#pragma unroll
        for (int kc = 0; kc < 2; kc++) {
            const int kb = kc * 8;
            u32 af[4][4];
#pragma unroll
            for (int mi = 0; mi < 4; mi++) {
                const u32* ap0 = &As[(m0w + mi * 16 + g) * ASTRIDE + kb + tk];
                const u32* ap1 = &As[(m0w + mi * 16 + g + 8) * ASTRIDE + kb + tk];
                af[mi][0] = ap0[0];
                af[mi][1] = ap1[0];
                af[mi][2] = ap0[4];
                af[mi][3] = ap1[4];
            }
            u32 bf[4][2];
#pragma unroll
            for (int ni = 0; ni < 4; ni++) {
                const u32* bp = &Bs[(kb + tk) * BSTRIDE + n0w + ni * 8 + g];
                bf[ni][0] = bp[0];
                bf[ni][1] = bp[4 * BSTRIDE];
            }
#pragma unroll
            for (int mi = 0; mi < 4; mi++)
#pragma unroll
                for (int ni = 0; ni < 4; ni++)
                    mma_tf32(acc[mi][ni][0], acc[mi][ni][1], acc[mi][ni][2], acc[mi][ni][3],
                             af[mi][0], af[mi][1], af[mi][2], af[mi][3],
                             bf[ni][0], bf[ni][1]);
        }
        __syncthreads();
    }

#pragma unroll
    for (int ni = 0; ni < 4; ni++) {
        const int n = bn + n0w + ni * 8 + tk * 2;
        const float2 bv = *(const float2*)&bias[n];
#pragma unroll
        for (int mi = 0; mi < 4; mi++) {
            const int mA = bm + m0w + mi * 16 + g;
            const int mB = mA + 8;
            const int bA = mA >> 8, tA = mA & 255;
            const int bA2 = mB >> 8, tB = mB & 255;
            float2 o0 = make_float2(acc[mi][ni][0] + bv.x, acc[mi][ni][1] + bv.y);
            float2 o1 = make_float2(acc[mi][ni][2] + bv.x, acc[mi][ni][3] + bv.y);
            *(float2*)&GX[((long long)tA * BB + bA) * NG + n] = o0;
            *(float2*)&GX[((long long)tB * BB + bA2) * NG + n] = o1;
        }
    }
}

// ---------------- Phase 2: persistent scan with tf32 mma ----------------
#define NBLK 128
#define HS_STRIDE 516
#define WS_U32 (4 * 64 * 64)        // 16384
#define HS_U32 (BB * HS_STRIDE)     // 33024
#define GH_STRIDE 34
#define GH_F32 (BB * GH_STRIDE)     // 2176
#define SMEM_BYTES ((WS_U32 + HS_U32 + GH_F32) * 4)

// R7 atomic barrier: per-CTA atomics pipeline and overlap with CTA skew;
// only the last arrival's atomic + one release hop are on the critical path.
__device__ __forceinline__ void grid_barrier() {
    __syncthreads();
    if (threadIdx.x == 0) {
        u32 gen;
        asm volatile("ld.relaxed.gpu.u32 %0, [%1];" : "=r"(gen) : "l"(&g_bar_gen) : "memory");
        u32 old;
        asm volatile("atom.add.acq_rel.gpu.u32 %0, [%1], 1;" : "=r"(old) : "l"(&g_bar_count) : "memory");
        if (old == NBLK - 1) {
            asm volatile("st.relaxed.gpu.u32 [%0], 0;" :: "l"(&g_bar_count) : "memory");
            u32 ng = gen + 1;
            asm volatile("st.release.gpu.u32 [%0], %1;" :: "l"(&g_bar_gen), "r"(ng) : "memory");
        } else {
            u32 cur;
            do {
                asm volatile("ld.acquire.gpu.u32 %0, [%1];" : "=r"(cur) : "l"(&g_bar_gen) : "memory");
            } while (cur == gen);
        }
    }
    __syncthreads();
}

__device__ __forceinline__ float sigmoidf_(float x) {
    return 1.f / (1.f + expf(-x));
}
__device__ __forceinline__ float softplusf_(float x) {
    return fmaxf(x, 0.f) + log1pf(expf(-fabsf(x)));
}

__global__ __launch_bounds__(512, 1) void scan_kernel(
    const float* __restrict__ GX,    // [T][B][3584]
    const float* __restrict__ dtime, // [B,T]
    const float* __restrict__ W,     // [1024, 3584]
    float* out)                      // h_ts[B,T,H] then decay[B,T,4,H]
{
    extern __shared__ u32 smem_u[];
    u32* Ws = smem_u;                       // [4][64][64]
    u32* hs = smem_u + WS_U32;              // [64][516]
    float* gh = (float*)(smem_u + WS_U32 + HS_U32);  // [64][34]

    const int tid = threadIdx.x;
    const int blk = blockIdx.x;
    const int c0 = blk * 4;

    const int w = tid >> 5;
    const int l = tid & 31;
    const int mt = w & 3;
    const int nt = w >> 2;
    const int m0 = mt * 16;
    const int g = l >> 2;
    const int tk = l & 3;

    const int r = tid & 255;
    const int b = r >> 2;
    const int cc = r & 3;
    const int c = c0 + cc;

    // one-time init: W_h fragments (tf32, lane order) + zero gh
    for (int i = tid; i < WS_U32; i += 512) {
        int slot = i & 1;
        int l2 = (i >> 1) & 31;
        int ks = (i >> 6) & 63;
        int nt2 = i >> 12;
        int k = ks * 8 + (l2 & 3) + slot * 4;
        int j = l2 >> 2;
        float v = 0.f;
        if (j < 7) v = W[(long long)(KK + k) * NG + j * HH + c0 + nt2];
        Ws[i] = f2tf32(v);
    }
    for (int i = tid; i < GH_F32; i += 512) gh[i] = 0.f;
    __syncthreads();

    float cf_r = 0.f;
    float cb_r = 0.f;

    // ldmatrix lane address for A-fragments:
    // row = m0 + (l & 15), col offset = (l >> 4) * 4 floats
    const u32 hA_lm = (u32)__cvta_generic_to_shared(
        hs + (m0 + (l & 15)) * HS_STRIDE + ((l >> 4) & 1) * 4);
    const u32* wB  = Ws + nt * 64 * 64 + l * 2;
    const long long DEC0 = (long long)BB * TT * HH;

    // prefetch step-0 gate inputs
    float x0, x1, x2, x3, x4, x5, x6, dt;
    if (tid < 256) {
        const float* gx = GX + (long long)b * NG + c;
        x0 = gx[0 * HH];
        x1 = gx[1 * HH];
        x2 = gx[2 * HH];
        x3 = gx[3 * HH];
        x4 = gx[4 * HH];
        x5 = gx[5 * HH];
        x6 = gx[6 * HH];
        dt = dtime[b * TT];
    }

    for (int t = 0; t < TT; t++) {
        if (t > 0) {
            // stage h_{t-1} -> SMEM (tf32)
#pragma unroll
            for (int i = 0; i < 16; i++) {
                int lin = i * 512 + tid;
                int bb = lin >> 7;
                int q = lin & 127;
                float4 v = *(const float4*)&out[((long long)bb * TT + (t - 1)) * HH + q * 4];
                uint4 u;
                u.x = f2tf32(v.x);
                u.y = f2tf32(v.y);
                u.z = f2tf32(v.z);
                u.w = f2tf32(v.w);
                *(uint4*)&hs[bb * HS_STRIDE + q * 4] = u;
            }
            __syncthreads();

            float acc0 = 0.f, acc1 = 0.f, acc2 = 0.f, acc3 = 0.f;
#pragma unroll 8
            for (int ks = 0; ks < 64; ks++) {
                u32 a0, a1, a2, a3;
                asm volatile(
                    "ldmatrix.sync.aligned.m8n8.x4.shared.b16 {%0,%1,%2,%3}, [%4];"
                    : "=r"(a0), "=r"(a1), "=r"(a2), "=r"(a3)
                    : "r"(hA_lm + ks * 32));
                uint2 bfr = *(const uint2*)(wB + ks * 64);
                mma_tf32(acc0, acc1, acc2, acc3, a0, a1, a2, a3, bfr.x, bfr.y);
            }

            const int col = nt * 8 + tk * 2;
            *(float2*)&gh[(m0 + g) * GH_STRIDE + col] = make_float2(acc0, acc1);
            *(float2*)&gh[(m0 + g + 8) * GH_STRIDE + col] = make_float2(acc2, acc3);
            __syncthreads();
        }

        if (tid < 256) {
            const float* ghr = &gh[b * GH_STRIDE + cc * 8];
            const float g0 = x0 + ghr[0];
            const float g1 = x1 + ghr[1];
            const float g2 = x2 + ghr[2];
            const float g3 = x3 + ghr[3];
            const float g4 = x4 + ghr[4];
            const float g5 = x5 + ghr[5];
            const float g6 = x6 + ghr[6];

            const float gate_i  = sigmoidf_(g0);
            const float gate_f  = sigmoidf_(g1);
            const float gate_o  = sigmoidf_(g2);
            const float gate_ib = sigmoidf_(g3);
            const float gate_fb = sigmoidf_(g4);
            const float gate_d  = softplusf_(g5);
            const float z       = tanhf(g6);

            const float c_t  = gate_f  * cf_r + gate_i  * z;
            const float cb_t = gate_fb * cb_r + gate_ib * z;
            const float cfn  = cb_t + (c_t - cb_t) * expf(-gate_d * dt);
            const float h_t  = gate_o * tanhf(cfn);

            cf_r = cfn;
            cb_r = cb_t;

            out[((long long)b * TT + t) * HH + c] = h_t;
            float* dec = out + DEC0 + ((long long)(b * TT + t) * 4) * HH + c;
            dec[0 * HH] = c_t;
            dec[1 * HH] = cb_t;
            dec[2 * HH] = gate_d;
            dec[3 * HH] = gate_o;

            // prefetch next step's gate inputs; latency hides in the barrier
            if (t + 1 < TT) {
                const float* gx = GX + ((long long)(t + 1) * BB + b) * NG + c;
                x0 = gx[0 * HH];
                x1 = gx[1 * HH];
                x2 = gx[2 * HH];
                x3 = gx[3 * HH];
                x4 = gx[4 * HH];
                x5 = gx[5 * HH];
                x6 = gx[6 * HH];
                dt = dtime[b * TT + t + 1];
            }
        }

        if (t + 1 < TT) grid_barrier();
    }
}

// ---------------- launch ----------------
extern "C" void kernel_launch(void* const* d_in, const int* in_sizes, int n_in,
                              void* d_out, int out_size) {
    (void)in_sizes; (void)n_in; (void)out_size;
    const float* X     = (const float*)d_in[0];  // seq_type_embed [B,T,H]
    const float* dtime = (const float*)d_in[1];  // [B,T]
    const float* W     = (const float*)d_in[2];  // [2H, 7H]
    const float* bias  = (const float*)d_in[3];  // [7H]
    float* out = (float*)d_out;

    float* GX;
    cudaGetSymbolAddress((void**)&GX, g_gx);

    // Phase 1: tf32 mma GEMM for x-part pre-activations
    dim3 grid1(NG / TBN, (BB * TT) / TBM);   // (28, 128)
    gemm_gx_tf32<<<grid1, 256>>>(X, W, bias, GX);

    // Phase 2: one persistent kernel for the whole scan
    cudaFuncSetAttribute(scan_kernel, cudaFuncAttributeMaxDynamicSharedMemorySize,
                         SMEM_BYTES);
    scan_kernel<<<NBLK, 512, SMEM_BYTES>>>(GX, dtime, W, out);
}

// round 11
// speedup vs baseline: 1.2534x; 1.0460x over previous
#include <cuda_runtime.h>
#include <math.h>

// Problem constants
#define BB 64      // batch
#define TT 256     // time steps
#define HH 512     // hidden
#define NG 3584    // 7*H gate width
#define KK 512     // per-half K (x part / h part each 512)

typedef unsigned long long u64;
typedef unsigned int u32;

// ---------------- tf32 mma helpers ----------------
__device__ __forceinline__ u32 f2tf32(float f) {
    u32 u; asm("cvt.rna.tf32.f32 %0, %1;" : "=r"(u) : "f"(f)); return u;
}
__device__ __forceinline__ void mma_tf32(float &c0, float &c1, float &c2, float &c3,
                                         u32 a0, u32 a1, u32 a2, u32 a3,
                                         u32 b0, u32 b1) {
    asm("mma.sync.aligned.m16n8k8.row.col.f32.tf32.tf32.f32 "
        "{%0,%1,%2,%3},{%4,%5,%6,%7},{%8,%9},{%0,%1,%2,%3};"
        : "+f"(c0), "+f"(c1), "+f"(c2), "+f"(c3)
        : "r"(a0), "r"(a1), "r"(a2), "r"(a3), "r"(b0), "r"(b1));
}
__device__ __forceinline__ void cp16(u32 dst_smem, const void* src) {
    asm volatile("cp.async.ca.shared.global [%0], [%1], 16;"
                 :: "r"(dst_smem), "l"(src) : "memory");
}

// ---------------- scratch (no allocations allowed) ----------------
// GX layout: [t][b][n], n = j*512 + c  (x-part pre-activations + bias)
__device__ float g_gx[(long long)BB * TT * NG];   // ~224MB
__device__ u32 g_bar_count = 0;
__device__ u32 g_bar_gen = 0;

// ---------------- Phase 1: GX = X @ W[0:512] + b, tf32 mma + cp.async ------
#define TBM 128
#define TBN 128
#define TBK 16
#define ASTRIDE 20      // As [m][16+4]
#define BSTRIDE 136     // Bs [k][128+8]
#define NIT (KK / TBK)  // 32

__global__ __launch_bounds__(256, 1) void gemm_gx_tf32(
    const float* __restrict__ X,   // [B*T, 512]
    const float* __restrict__ W,   // [1024, 3584]
    const float* __restrict__ bias,// [3584]
    float* __restrict__ GX)        // [T][B][3584]
{
    __shared__ float As[2][TBM * ASTRIDE];
    __shared__ float Bs[2][TBK * BSTRIDE];

    const int tid = threadIdx.x;
    const int bm = blockIdx.y * TBM;
    const int bn = blockIdx.x * TBN;
    const int w = tid >> 5, l = tid & 31;
    const int wr = w >> 2, wc = w & 3;
    const int m0w = wr * 64, n0w = wc * 32;
    const int g = l >> 2, tk = l & 3;

    // async-copy maps: A 2x16B per thread, B 2x16B per thread
    const int arow = tid >> 1;            // 0..127
    const int acol = (tid & 1) * 8;       // 0 or 8
    const int brow = tid >> 4;            // 0..15
    const int bcol = (tid & 15) * 8;      // 0..120

    const float* Ag = X + (long long)(bm + arow) * KK + acol;
    const float* Bg = W + (long long)brow * NG + bn + bcol;

    u32 aDst[2], bDst[2];
    aDst[0] = (u32)__cvta_generic_to_shared(&As[0][arow * ASTRIDE + acol]);
    aDst[1] = (u32)__cvta_generic_to_shared(&As[1][arow * ASTRIDE + acol]);
    bDst[0] = (u32)__cvta_generic_to_shared(&Bs[0][brow * BSTRIDE + bcol]);
    bDst[1] = (u32)__cvta_generic_to_shared(&Bs[1][brow * BSTRIDE + bcol]);

    float acc[4][4][4];
#pragma unroll
    for (int mi = 0; mi < 4; mi++)
#pragma unroll
        for (int ni = 0; ni < 4; ni++)
#pragma unroll
            for (int q = 0; q < 4; q++) acc[mi][ni][q] = 0.f;

    // prime buffer 0
    cp16(aDst[0], Ag);
    cp16(aDst[0] + 16, Ag + 4);
    cp16(bDst[0], Bg);
    cp16(bDst[0] + 16, Bg + 4);
    asm volatile("cp.async.commit_group;" ::: "memory");

    int buf = 0;
    for (int it = 0; it < NIT; it++) {
        if (it + 1 < NIT) {
            const float* An = Ag + (it + 1) * TBK;
            const float* Bn = Bg + (long long)(it + 1) * TBK * NG;
            const int nb = buf ^ 1;
            cp16(aDst[nb], An);
            cp16(aDst[nb] + 16, An + 4);
            cp16(bDst[nb], Bn);
            cp16(bDst[nb] + 16, Bn + 4);
            asm volatile("cp.async.commit_group;" ::: "memory");
            asm volatile("cp.async.wait_group 1;" ::: "memory");
        } else {
            asm volatile("cp.async.wait_group 0;" ::: "memory");
        }
        __syncthreads();

        const float* as = As[buf];
        const float* bs = Bs[buf];
#pragma unroll
        for (int kc = 0; kc < 2; kc++) {
            const int kb = kc * 8;
            u32 af[4][4];
#pragma unroll
            for (int mi = 0; mi < 4; mi++) {
                const float* ap0 = &as[(m0w + mi * 16 + g) * ASTRIDE + kb + tk];
                const float* ap1 = &as[(m0w + mi * 16 + g + 8) * ASTRIDE + kb + tk];
                af[mi][0] = f2tf32(ap0[0]);
                af[mi][1] = f2tf32(ap1[0]);
                af[mi][2] = f2tf32(ap0[4]);
                af[mi][3] = f2tf32(ap1[4]);
            }
            u32 bf[4][2];
#pragma unroll
            for (int ni = 0; ni < 4; ni++) {
                const float* bp = &bs[(kb + tk) * BSTRIDE + n0w + ni * 8 + g];
                bf[ni][0] = f2tf32(bp[0]);
                bf[ni][1] = f2tf32(bp[4 * BSTRIDE]);
            }
#pragma unroll
            for (int mi = 0; mi < 4; mi++)
#pragma unroll
                for (int ni = 0; ni < 4; ni++)
                    mma_tf32(acc[mi][ni][0], acc[mi][ni][1], acc[mi][ni][2], acc[mi][ni][3],
                             af[mi][0], af[mi][1], af[mi][2], af[mi][3],
                             bf[ni][0], bf[ni][1]);
        }
        __syncthreads();   // done reading buf before it is refilled
        buf ^= 1;
    }

#pragma unroll
    for (int ni = 0; ni < 4; ni++) {
        const int n = bn + n0w + ni * 8 + tk * 2;
        const float2 bv = *(const float2*)&bias[n];
#pragma unroll
        for (int mi = 0; mi < 4; mi++) {
            const int mA = bm + m0w + mi * 16 + g;
            const int mB = mA + 8;
            const int bA = mA >> 8, tA = mA & 255;
            const int bA2 = mB >> 8, tB = mB & 255;
            float2 o0 = make_float2(acc[mi][ni][0] + bv.x, acc[mi][ni][1] + bv.y);
            float2 o1 = make_float2(acc[mi][ni][2] + bv.x, acc[mi][ni][3] + bv.y);
            *(float2*)&GX[((long long)tA * BB + bA) * NG + n] = o0;
            *(float2*)&GX[((long long)tB * BB + bA2) * NG + n] = o1;
        }
    }
}

// ---------------- Phase 2: persistent scan with tf32 mma ----------------
#define NBLK 128
#define HS_STRIDE 516
#define WS_U32 (4 * 64 * 64)        // 16384
#define HS_U32 (BB * HS_STRIDE)     // 33024
#define GH_STRIDE 34
#define GH_F32 (BB * GH_STRIDE)     // 2176
#define SMEM_BYTES ((WS_U32 + HS_U32 + GH_F32) * 4)

// Atomic barrier: per-CTA atomics pipeline and overlap with CTA skew;
// only the last arrival's atomic + one release hop are on the critical path.
__device__ __forceinline__ void grid_barrier() {
    __syncthreads();
    if (threadIdx.x == 0) {
        u32 gen;
        asm volatile("ld.relaxed.gpu.u32 %0, [%1];" : "=r"(gen) : "l"(&g_bar_gen) : "memory");
        u32 old;
        asm volatile("atom.add.acq_rel.gpu.u32 %0, [%1], 1;" : "=r"(old) : "l"(&g_bar_count) : "memory");
        if (old == NBLK - 1) {
            asm volatile("st.relaxed.gpu.u32 [%0], 0;" :: "l"(&g_bar_count) : "memory");
            u32 ng = gen + 1;
            asm volatile("st.release.gpu.u32 [%0], %1;" :: "l"(&g_bar_gen), "r"(ng) : "memory");
        } else {
            u32 cur;
            do {
                asm volatile("ld.acquire.gpu.u32 %0, [%1];" : "=r"(cur) : "l"(&g_bar_gen) : "memory");
            } while (cur == gen);
        }
    }
    __syncthreads();
}

__device__ __forceinline__ float sigmoidf_(float x) {
    return 1.f / (1.f + expf(-x));
}
__device__ __forceinline__ float softplusf_(float x) {
    return fmaxf(x, 0.f) + log1pf(expf(-fabsf(x)));
}

__global__ __launch_bounds__(512, 1) void scan_kernel(
    const float* __restrict__ GX,    // [T][B][3584]
    const float* __restrict__ dtime, // [B,T]
    const float* __restrict__ W,     // [1024, 3584]
    float* out)                      // h_ts[B,T,H] then decay[B,T,4,H]
{
    extern __shared__ u32 smem_u[];
    u32* Ws = smem_u;                       // [4][64][64]
    u32* hs = smem_u + WS_U32;              // [64][516]
    float* gh = (float*)(smem_u + WS_U32 + HS_U32);  // [64][34]

    const int tid = threadIdx.x;
    const int blk = blockIdx.x;
    const int c0 = blk * 4;

    const int w = tid >> 5;
    const int l = tid & 31;
    const int mt = w & 3;
    const int nt = w >> 2;
    const int m0 = mt * 16;
    const int g = l >> 2;
    const int tk = l & 3;

    const int r = tid & 255;
    const int b = r >> 2;
    const int cc = r & 3;
    const int c = c0 + cc;

    // one-time init: W_h fragments (tf32, lane order) + zero gh
    for (int i = tid; i < WS_U32; i += 512) {
        int slot = i & 1;
        int l2 = (i >> 1) & 31;
        int ks = (i >> 6) & 63;
        int nt2 = i >> 12;
        int k = ks * 8 + (l2 & 3) + slot * 4;
        int j = l2 >> 2;
        float v = 0.f;
        if (j < 7) v = W[(long long)(KK + k) * NG + j * HH + c0 + nt2];
        Ws[i] = f2tf32(v);
    }
    for (int i = tid; i < GH_F32; i += 512) gh[i] = 0.f;
    __syncthreads();

    float cf_r = 0.f;
    float cb_r = 0.f;

    // ldmatrix lane address for A-fragments:
    // row = m0 + (l & 15), col offset = (l >> 4) * 4 floats
    const u32 hA_lm = (u32)__cvta_generic_to_shared(
        hs + (m0 + (l & 15)) * HS_STRIDE + ((l >> 4) & 1) * 4);
    const u32* wB  = Ws + nt * 64 * 64 + l * 2;
    const long long DEC0 = (long long)BB * TT * HH;

    // prefetch step-0 gate inputs
    float x0, x1, x2, x3, x4, x5, x6, dt;
    if (tid < 256) {
        const float* gx = GX + (long long)b * NG + c;
        x0 = gx[0 * HH];
        x1 = gx[1 * HH];
        x2 = gx[2 * HH];
        x3 = gx[3 * HH];
        x4 = gx[4 * HH];
        x5 = gx[5 * HH];
        x6 = gx[6 * HH];
        dt = dtime[b * TT];
    }

    for (int t = 0; t < TT; t++) {
        if (t > 0) {
            // stage h_{t-1} -> SMEM (tf32)
#pragma unroll
            for (int i = 0; i < 16; i++) {
                int lin = i * 512 + tid;
                int bb = lin >> 7;
                int q = lin & 127;
                float4 v = *(const float4*)&out[((long long)bb * TT + (t - 1)) * HH + q * 4];
                uint4 u;
                u.x = f2tf32(v.x);
                u.y = f2tf32(v.y);
                u.z = f2tf32(v.z);
                u.w = f2tf32(v.w);
                *(uint4*)&hs[bb * HS_STRIDE + q * 4] = u;
            }
            __syncthreads();

            // two independent accumulator chains (even/odd ks) to halve the
            // dependent-HMMA latency chain
            float pa0 = 0.f, pa1 = 0.f, pa2 = 0.f, pa3 = 0.f;
            float pb0 = 0.f, pb1 = 0.f, pb2 = 0.f, pb3 = 0.f;
#pragma unroll 4
            for (int ks = 0; ks < 64; ks += 2) {
                u32 a0, a1, a2, a3;
                asm volatile(
                    "ldmatrix.sync.aligned.m8n8.x4.shared.b16 {%0,%1,%2,%3}, [%4];"
                    : "=r"(a0), "=r"(a1), "=r"(a2), "=r"(a3)
                    : "r"(hA_lm + ks * 32));
                uint2 bfr = *(const uint2*)(wB + ks * 64);
                mma_tf32(pa0, pa1, pa2, pa3, a0, a1, a2, a3, bfr.x, bfr.y);

                u32 e0, e1, e2, e3;
                asm volatile(
                    "ldmatrix.sync.aligned.m8n8.x4.shared.b16 {%0,%1,%2,%3}, [%4];"
                    : "=r"(e0), "=r"(e1), "=r"(e2), "=r"(e3)
                    : "r"(hA_lm + (ks + 1) * 32));
                uint2 bf2 = *(const uint2*)(wB + (ks + 1) * 64);
                mma_tf32(pb0, pb1, pb2, pb3, e0, e1, e2, e3, bf2.x, bf2.y);
            }
            const float acc0 = pa0 + pb0;
            const float acc1 = pa1 + pb1;
            const float acc2 = pa2 + pb2;
            const float acc3 = pa3 + pb3;

            const int col = nt * 8 + tk * 2;
            *(float2*)&gh[(m0 + g) * GH_STRIDE + col] = make_float2(acc0, acc1);
            *(float2*)&gh[(m0 + g + 8) * GH_STRIDE + col] = make_float2(acc2, acc3);
            __syncthreads();
        }

        if (tid < 256) {
            const float* ghr = &gh[b * GH_STRIDE + cc * 8];
            const float g0 = x0 + ghr[0];
            const float g1 = x1 + ghr[1];
            const float g2 = x2 + ghr[2];
            const float g3 = x3 + ghr[3];
            const float g4 = x4 + ghr[4];
            const float g5 = x5 + ghr[5];
            const float g6 = x6 + ghr[6];

            const float gate_i  = sigmoidf_(g0);
            const float gate_f  = sigmoidf_(g1);
            const float gate_o  = sigmoidf_(g2);
            const float gate_ib = sigmoidf_(g3);
            const float gate_fb = sigmoidf_(g4);
            const float gate_d  = softplusf_(g5);
            const float z       = tanhf(g6);

            const float c_t  = gate_f  * cf_r + gate_i  * z;
            const float cb_t = gate_fb * cb_r + gate_ib * z;
            const float cfn  = cb_t + (c_t - cb_t) * expf(-gate_d * dt);
            const float h_t  = gate_o * tanhf(cfn);

            cf_r = cfn;
            cb_r = cb_t;

            out[((long long)b * TT + t) * HH + c] = h_t;
            float* dec = out + DEC0 + ((long long)(b * TT + t) * 4) * HH + c;
            dec[0 * HH] = c_t;
            dec[1 * HH] = cb_t;
            dec[2 * HH] = gate_d;
            dec[3 * HH] = gate_o;

            // prefetch next step's gate inputs; latency hides in the barrier
            if (t + 1 < TT) {
                const float* gx = GX + ((long long)(t + 1) * BB + b) * NG + c;
                x0 = gx[0 * HH];
                x1 = gx[1 * HH];
                x2 = gx[2 * HH];
                x3 = gx[3 * HH];
                x4 = gx[4 * HH];
                x5 = gx[5 * HH];
                x6 = gx[6 * HH];
                dt = dtime[b * TT + t + 1];
            }
        }

        if (t + 1 < TT) grid_barrier();
    }
}

// ---------------- launch ----------------
extern "C" void kernel_launch(void* const* d_in, const int* in_sizes, int n_in,
                              void* d_out, int out_size) {
    (void)in_sizes; (void)n_in; (void)out_size;
    const float* X     = (const float*)d_in[0];  // seq_type_embed [B,T,H]
    const float* dtime = (const float*)d_in[1];  // [B,T]
    const float* W     = (const float*)d_in[2];  // [2H, 7H]
    const float* bias  = (const float*)d_in[3];  // [7H]
    float* out = (float*)d_out;

    float* GX;
    cudaGetSymbolAddress((void**)&GX, g_gx);

    // Phase 1: tf32 mma GEMM for x-part pre-activations (cp.async pipelined)
    dim3 grid1(NG / TBN, (BB * TT) / TBM);   // (28, 128)
    gemm_gx_tf32<<<grid1, 256>>>(X, W, bias, GX);

    // Phase 2: one persistent kernel for the whole scan
    cudaFuncSetAttribute(scan_kernel, cudaFuncAttributeMaxDynamicSharedMemorySize,
                         SMEM_BYTES);
    scan_kernel<<<NBLK, 512, SMEM_BYTES>>>(GX, dtime, W, out);
}

// round 13
// speedup vs baseline: 1.4490x; 1.1561x over previous
#include <cuda_runtime.h>
#include <math.h>

// Problem constants
#define BB 64      // batch
#define TT 256     // time steps
#define HH 512     // hidden
#define NG 3584    // 7*H gate width
#define KK 512     // per-half K (x part / h part each 512)

typedef unsigned long long u64;
typedef unsigned int u32;

// ---------------- tf32 mma helpers ----------------
__device__ __forceinline__ u32 f2tf32(float f) {
    u32 u; asm("cvt.rna.tf32.f32 %0, %1;" : "=r"(u) : "f"(f)); return u;
}
__device__ __forceinline__ void mma_tf32(float &c0, float &c1, float &c2, float &c3,
                                         u32 a0, u32 a1, u32 a2, u32 a3,
                                         u32 b0, u32 b1) {
    asm("mma.sync.aligned.m16n8k8.row.col.f32.tf32.tf32.f32 "
        "{%0,%1,%2,%3},{%4,%5,%6,%7},{%8,%9},{%0,%1,%2,%3};"
        : "+f"(c0), "+f"(c1), "+f"(c2), "+f"(c3)
        : "r"(a0), "r"(a1), "r"(a2), "r"(a3), "r"(b0), "r"(b1));
}
__device__ __forceinline__ void cp16(u32 dst_smem, const void* src) {
    asm volatile("cp.async.ca.shared.global [%0], [%1], 16;"
                 :: "r"(dst_smem), "l"(src) : "memory");
}

// ---------------- scratch (no allocations allowed) ----------------
// GX layout: [t][b][n], n = j*512 + c  (x-part pre-activations + bias)
__device__ float g_gx[(long long)BB * TT * NG];   // ~224MB
__device__ u32 g_bar_count = 0;
__device__ u32 g_bar_gen = 0;

// ---------------- Phase 1: GX = X @ W[0:512] + b, tf32 mma + cp.async ------
#define TBM 128
#define TBN 128
#define TBK 16
#define ASTRIDE 20      // As [m][16+4]
#define BSTRIDE 136     // Bs [k][128+8]
#define NIT (KK / TBK)  // 32

__global__ __launch_bounds__(256, 1) void gemm_gx_tf32(
    const float* __restrict__ X,   // [B*T, 512]
    const float* __restrict__ W,   // [1024, 3584]
    const float* __restrict__ bias,// [3584]
    float* __restrict__ GX)        // [T][B][3584]
{
    __shared__ float As[2][TBM * ASTRIDE];
    __shared__ float Bs[2][TBK * BSTRIDE];

    const int tid = threadIdx.x;
    const int bm = blockIdx.y * TBM;
    const int bn = blockIdx.x * TBN;
    const int w = tid >> 5, l = tid & 31;
    const int wr = w >> 2, wc = w & 3;
    const int m0w = wr * 64, n0w = wc * 32;
    const int g = l >> 2, tk = l & 3;

    const int arow = tid >> 1;            // 0..127
    const int acol = (tid & 1) * 8;       // 0 or 8
    const int brow = tid >> 4;            // 0..15
    const int bcol = (tid & 15) * 8;      // 0..120

    const float* Ag = X + (long long)(bm + arow) * KK + acol;
    const float* Bg = W + (long long)brow * NG + bn + bcol;

    u32 aDst[2], bDst[2];
    aDst[0] = (u32)__cvta_generic_to_shared(&As[0][arow * ASTRIDE + acol]);
    aDst[1] = (u32)__cvta_generic_to_shared(&As[1][arow * ASTRIDE + acol]);
    bDst[0] = (u32)__cvta_generic_to_shared(&Bs[0][brow * BSTRIDE + bcol]);
    bDst[1] = (u32)__cvta_generic_to_shared(&Bs[1][brow * BSTRIDE + bcol]);

    float acc[4][4][4];
#pragma unroll
    for (int mi = 0; mi < 4; mi++)
#pragma unroll
        for (int ni = 0; ni < 4; ni++)
#pragma unroll
            for (int q = 0; q < 4; q++) acc[mi][ni][q] = 0.f;

    cp16(aDst[0], Ag);
    cp16(aDst[0] + 16, Ag + 4);
    cp16(bDst[0], Bg);
    cp16(bDst[0] + 16, Bg + 4);
    asm volatile("cp.async.commit_group;" ::: "memory");

    int buf = 0;
    for (int it = 0; it < NIT; it++) {
        if (it + 1 < NIT) {
            const float* An = Ag + (it + 1) * TBK;
            const float* Bn = Bg + (long long)(it + 1) * TBK * NG;
            const int nb = buf ^ 1;
            cp16(aDst[nb], An);
            cp16(aDst[nb] + 16, An + 4);
            cp16(bDst[nb], Bn);
            cp16(bDst[nb] + 16, Bn + 4);
            asm volatile("cp.async.commit_group;" ::: "memory");
            asm volatile("cp.async.wait_group 1;" ::: "memory");
        } else {
            asm volatile("cp.async.wait_group 0;" ::: "memory");
        }
        __syncthreads();

        const float* as = As[buf];
        const float* bs = Bs[buf];
#pragma unroll
        for (int kc = 0; kc < 2; kc++) {
            const int kb = kc * 8;
            u32 af[4][4];
#pragma unroll
            for (int mi = 0; mi < 4; mi++) {
                const float* ap0 = &as[(m0w + mi * 16 + g) * ASTRIDE + kb + tk];
                const float* ap1 = &as[(m0w + mi * 16 + g + 8) * ASTRIDE + kb + tk];
                af[mi][0] = f2tf32(ap0[0]);
                af[mi][1] = f2tf32(ap1[0]);
                af[mi][2] = f2tf32(ap0[4]);
                af[mi][3] = f2tf32(ap1[4]);
            }
            u32 bf[4][2];
#pragma unroll
            for (int ni = 0; ni < 4; ni++) {
                const float* bp = &bs[(kb + tk) * BSTRIDE + n0w + ni * 8 + g];
                bf[ni][0] = f2tf32(bp[0]);
                bf[ni][1] = f2tf32(bp[4 * BSTRIDE]);
            }
#pragma unroll
            for (int mi = 0; mi < 4; mi++)
#pragma unroll
                for (int ni = 0; ni < 4; ni++)
                    mma_tf32(acc[mi][ni][0], acc[mi][ni][1], acc[mi][ni][2], acc[mi][ni][3],
                             af[mi][0], af[mi][1], af[mi][2], af[mi][3],
                             bf[ni][0], bf[ni][1]);
        }
        __syncthreads();
        buf ^= 1;
    }

#pragma unroll
    for (int ni = 0; ni < 4; ni++) {
        const int n = bn + n0w + ni * 8 + tk * 2;
        const float2 bv = *(const float2*)&bias[n];
#pragma unroll
        for (int mi = 0; mi < 4; mi++) {
            const int mA = bm + m0w + mi * 16 + g;
            const int mB = mA + 8;
            const int bA = mA >> 8, tA = mA & 255;
            const int bA2 = mB >> 8, tB = mB & 255;
            float2 o0 = make_float2(acc[mi][ni][0] + bv.x, acc[mi][ni][1] + bv.y);
            float2 o1 = make_float2(acc[mi][ni][2] + bv.x, acc[mi][ni][3] + bv.y);
            *(float2*)&GX[((long long)tA * BB + bA) * NG + n] = o0;
            *(float2*)&GX[((long long)tB * BB + bA2) * NG + n] = o1;
        }
    }
}

// ---------------- Phase 2: persistent scan with tf32 mma ----------------
// 128 CTAs = 64 column-groups x 2 batch-halves. CTA owns 8 h-columns and
// 32 batch rows: stages only its 32 rows of h (66KB, HALF the prior L2
// traffic) but holds W_h fragments for 8 columns (128KB SMEM, one-time).
// Warps: mt = w&1 (16-row m-tile of the 32 local rows), nt = w>>1 (column
// within the 8; virtual n = nt*8 + gate j, j==7 pad).
#define NBLK 128
#define HROWS 32
#define HS_STRIDE 516
#define WS_U32 (8 * 64 * 64)            // 32768 (8 columns x 16KB)
#define HS_U32 (HROWS * HS_STRIDE)      // 16512
#define GH_STRIDE 66
#define GH_F32 (HROWS * GH_STRIDE)      // 2112
#define SMEM_BYTES ((WS_U32 + HS_U32 + GH_F32) * 4)   // 205568

// Atomic barrier: per-CTA atomics pipeline and overlap with CTA skew;
// only the last arrival's atomic + one release hop are on the critical path.
__device__ __forceinline__ void grid_barrier() {
    __syncthreads();
    if (threadIdx.x == 0) {
        u32 gen;
        asm volatile("ld.relaxed.gpu.u32 %0, [%1];" : "=r"(gen) : "l"(&g_bar_gen) : "memory");
        u32 old;
        asm volatile("atom.add.acq_rel.gpu.u32 %0, [%1], 1;" : "=r"(old) : "l"(&g_bar_count) : "memory");
        if (old == NBLK - 1) {
            asm volatile("st.relaxed.gpu.u32 [%0], 0;" :: "l"(&g_bar_count) : "memory");
            u32 ng = gen + 1;
            asm volatile("st.release.gpu.u32 [%0], %1;" :: "l"(&g_bar_gen), "r"(ng) : "memory");
        } else {
            u32 cur;
            do {
                asm volatile("ld.acquire.gpu.u32 %0, [%1];" : "=r"(cur) : "l"(&g_bar_gen) : "memory");
            } while (cur == gen);
        }
    }
    __syncthreads();
}

__device__ __forceinline__ float sigmoidf_(float x) {
    return 1.f / (1.f + expf(-x));
}
__device__ __forceinline__ float softplusf_(float x) {
    return fmaxf(x, 0.f) + log1pf(expf(-fabsf(x)));
}

__global__ __launch_bounds__(512, 1) void scan_kernel(
    const float* __restrict__ GX,    // [T][B][3584]
    const float* __restrict__ dtime, // [B,T]
    const float* __restrict__ W,     // [1024, 3584]
    float* out)                      // h_ts[B,T,H] then decay[B,T,4,H]
{
    extern __shared__ u32 smem_u[];
    u32* Ws = smem_u;                       // [8][64][64]
    u32* hs = smem_u + WS_U32;              // [32][516]
    float* gh = (float*)(smem_u + WS_U32 + HS_U32);  // [32][66]

    const int tid = threadIdx.x;
    const int blk = blockIdx.x;
    const int colgrp = blk >> 1;           // 0..63
    const int bh = blk & 1;                // batch half
    const int c0 = colgrp * 8;
    const int bbase = bh * HROWS;

    const int w = tid >> 5;
    const int l = tid & 31;
    const int mt = w & 1;                  // m-tile (local rows mt*16..+15)
    const int nt = w >> 1;                 // 0..7 column within the 8
    const int m0 = mt * 16;
    const int g = l >> 2;
    const int tk = l & 3;

    // cell mapping (threads 0..255): local row b2, column cc within the 8
    const int r = tid & 255;
    const int b2 = r >> 3;                 // 0..31
    const int cc = r & 7;                  // 0..7
    const int b = bbase + b2;              // global batch row
    const int c = c0 + cc;                 // global h column

    // one-time init: W_h fragments (tf32, lane order) for 8 columns
    // Ws idx = nt2*4096 + ks*64 + l2*2 + slot:
    //   value = W_h[k = ks*8 + (l2&3) + slot*4][gate j = l2>>2, h-col c0+nt2]
    for (int i = tid; i < WS_U32; i += 512) {
        int slot = i & 1;
        int l2 = (i >> 1) & 31;
        int ks = (i >> 6) & 63;
        int nt2 = i >> 12;                 // 0..7
        int k = ks * 8 + (l2 & 3) + slot * 4;
        int j = l2 >> 2;
        float v = 0.f;
        if (j < 7) v = W[(long long)(KK + k) * NG + j * HH + c0 + nt2];
        Ws[i] = f2tf32(v);
    }
    for (int i = tid; i < GH_F32; i += 512) gh[i] = 0.f;
    __syncthreads();

    float cf_r = 0.f;
    float cb_r = 0.f;

    // ldmatrix lane address: row = m0 + (l & 15), col offset = (l>>4)*4
    const u32 hA_lm = (u32)__cvta_generic_to_shared(
        hs + (m0 + (l & 15)) * HS_STRIDE + ((l >> 4) & 1) * 4);
    const u32* wB  = Ws + nt * 4096 + l * 2;
    const long long DEC0 = (long long)BB * TT * HH;

    // prefetch step-0 gate inputs
    float x0, x1, x2, x3, x4, x5, x6, dt;
    if (tid < 256) {
        const float* gx = GX + (long long)b * NG + c;
        x0 = gx[0 * HH];
        x1 = gx[1 * HH];
        x2 = gx[2 * HH];
        x3 = gx[3 * HH];
        x4 = gx[4 * HH];
        x5 = gx[5 * HH];
        x6 = gx[6 * HH];
        dt = dtime[b * TT];
    }

    for (int t = 0; t < TT; t++) {
        if (t > 0) {
            // stage this CTA's 32 batch rows of h_{t-1} -> SMEM (tf32)
            // 32 rows x 128 float4 = 4096 float4 / 512 threads = 8 each
#pragma unroll
            for (int i = 0; i < 8; i++) {
                int lin = i * 512 + tid;
                int bb = lin >> 7;         // 0..31 local row
                int q = lin & 127;
                float4 v = *(const float4*)&out[((long long)(bbase + bb) * TT + (t - 1)) * HH + q * 4];
                uint4 u;
                u.x = f2tf32(v.x);
                u.y = f2tf32(v.y);
                u.z = f2tf32(v.z);
                u.w = f2tf32(v.w);
                *(uint4*)&hs[bb * HS_STRIDE + q * 4] = u;
            }
            __syncthreads();

            // two independent accumulator chains (even/odd ks)
            float pa0 = 0.f, pa1 = 0.f, pa2 = 0.f, pa3 = 0.f;
            float pb0 = 0.f, pb1 = 0.f, pb2 = 0.f, pb3 = 0.f;
#pragma unroll 4
            for (int ks = 0; ks < 64; ks += 2) {
                u32 a0, a1, a2, a3;
                asm volatile(
                    "ldmatrix.sync.aligned.m8n8.x4.shared.b16 {%0,%1,%2,%3}, [%4];"
                    : "=r"(a0), "=r"(a1), "=r"(a2), "=r"(a3)
                    : "r"(hA_lm + ks * 32));
                uint2 bfr = *(const uint2*)(wB + ks * 64);
                mma_tf32(pa0, pa1, pa2, pa3, a0, a1, a2, a3, bfr.x, bfr.y);

                u32 e0, e1, e2, e3;
                asm volatile(
                    "ldmatrix.sync.aligned.m8n8.x4.shared.b16 {%0,%1,%2,%3}, [%4];"
                    : "=r"(e0), "=r"(e1), "=r"(e2), "=r"(e3)
                    : "r"(hA_lm + (ks + 1) * 32));
                uint2 bf2 = *(const uint2*)(wB + (ks + 1) * 64);
                mma_tf32(pb0, pb1, pb2, pb3, e0, e1, e2, e3, bf2.x, bf2.y);
            }
            const float acc0 = pa0 + pb0;
            const float acc1 = pa1 + pb1;
            const float acc2 = pa2 + pb2;
            const float acc3 = pa3 + pb3;

            const int col = nt * 8 + tk * 2;     // virtual n 0..63
            *(float2*)&gh[(m0 + g) * GH_STRIDE + col] = make_float2(acc0, acc1);
            *(float2*)&gh[(m0 + g + 8) * GH_STRIDE + col] = make_float2(acc2, acc3);
            __syncthreads();
        }

        if (tid < 256) {
            const float* ghr = &gh[b2 * GH_STRIDE + cc * 8];
            const float g0 = x0 + ghr[0];
            const float g1 = x1 + ghr[1];
            const float g2 = x2 + ghr[2];
            const float g3 = x3 + ghr[3];
            const float g4 = x4 + ghr[4];
            const float g5 = x5 + ghr[5];
            const float g6 = x6 + ghr[6];

            const float gate_i  = sigmoidf_(g0);
            const float gate_f  = sigmoidf_(g1);
            const float gate_o  = sigmoidf_(g2);
            const float gate_ib = sigmoidf_(g3);
            const float gate_fb = sigmoidf_(g4);
            const float gate_d  = softplusf_(g5);
            const float z       = tanhf(g6);

            const float c_t  = gate_f  * cf_r + gate_i  * z;
            const float cb_t = gate_fb * cb_r + gate_ib * z;
            const float cfn  = cb_t + (c_t - cb_t) * expf(-gate_d * dt);
            const float h_t  = gate_o * tanhf(cfn);

            cf_r = cfn;
            cb_r = cb_t;

            out[((long long)b * TT + t) * HH + c] = h_t;
            float* dec = out + DEC0 + ((long long)(b * TT + t) * 4) * HH + c;
            dec[0 * HH] = c_t;
            dec[1 * HH] = cb_t;
            dec[2 * HH] = gate_d;
            dec[3 * HH] = gate_o;

            // prefetch next step's gate inputs; latency hides in the barrier
            if (t + 1 < TT) {
                const float* gx = GX + ((long long)(t + 1) * BB + b) * NG + c;
                x0 = gx[0 * HH];
                x1 = gx[1 * HH];
                x2 = gx[2 * HH];
                x3 = gx[3 * HH];
                x4 = gx[4 * HH];
                x5 = gx[5 * HH];
                x6 = gx[6 * HH];
                dt = dtime[b * TT + t + 1];
            }
        }

        if (t + 1 < TT) grid_barrier();
    }
}

// ---------------- launch ----------------
extern "C" void kernel_launch(void* const* d_in, const int* in_sizes, int n_in,
                              void* d_out, int out_size) {
    (void)in_sizes; (void)n_in; (void)out_size;
    const float* X     = (const float*)d_in[0];  // seq_type_embed [B,T,H]
    const float* dtime = (const float*)d_in[1];  // [B,T]
    const float* W     = (const float*)d_in[2];  // [2H, 7H]
    const float* bias  = (const float*)d_in[3];  // [7H]
    float* out = (float*)d_out;

    float* GX;
    cudaGetSymbolAddress((void**)&GX, g_gx);

    // Phase 1: tf32 mma GEMM for x-part pre-activations (cp.async pipelined)
    dim3 grid1(NG / TBN, (BB * TT) / TBM);   // (28, 128)
    gemm_gx_tf32<<<grid1, 256>>>(X, W, bias, GX);

    // Phase 2: one persistent kernel for the whole scan
    cudaFuncSetAttribute(scan_kernel, cudaFuncAttributeMaxDynamicSharedMemorySize,
                         SMEM_BYTES);
    scan_kernel<<<NBLK, 512, SMEM_BYTES>>>(GX, dtime, W, out);
}

// round 15
// speedup vs baseline: 1.4576x; 1.0059x over previous
#include <cuda_runtime.h>
#include <math.h>

// Problem constants
#define BB 64      // batch
#define TT 256     // time steps
#define HH 512     // hidden
#define NG 3584    // 7*H gate width
#define KK 512     // per-half K (x part / h part each 512)

typedef unsigned long long u64;
typedef unsigned int u32;

// ---------------- tf32 mma helpers ----------------
__device__ __forceinline__ u32 f2tf32(float f) {
    u32 u; asm("cvt.rna.tf32.f32 %0, %1;" : "=r"(u) : "f"(f)); return u;
}
__device__ __forceinline__ void mma_tf32(float &c0, float &c1, float &c2, float &c3,
                                         u32 a0, u32 a1, u32 a2, u32 a3,
                                         u32 b0, u32 b1) {
    asm("mma.sync.aligned.m16n8k8.row.col.f32.tf32.tf32.f32 "
        "{%0,%1,%2,%3},{%4,%5,%6,%7},{%8,%9},{%0,%1,%2,%3};"
        : "+f"(c0), "+f"(c1), "+f"(c2), "+f"(c3)
        : "r"(a0), "r"(a1), "r"(a2), "r"(a3), "r"(b0), "r"(b1));
}
__device__ __forceinline__ void cp16(u32 dst_smem, const void* src) {
    asm volatile("cp.async.ca.shared.global [%0], [%1], 16;"
                 :: "r"(dst_smem), "l"(src) : "memory");
}

// ---------------- scratch (no allocations allowed) ----------------
// GX layout: [t][b][n], n = j*512 + c  (x-part pre-activations + bias)
__device__ float g_gx[(long long)BB * TT * NG];   // ~224MB
// two independent 64-CTA barriers (one per batch half), separate lines
__device__ u32 g_bar_count[64];   // [0] and [32] used
__device__ u32 g_bar_gen[64];     // [0] and [32] used

// ---------------- Phase 1: GX = X @ W[0:512] + b, tf32 mma + cp.async ------
// 3-stage cp.async ring: 2 groups in flight, one __syncthreads per K-iter.
#define TBM 128
#define TBN 128
#define TBK 16
#define ASTRIDE 20      // As [m][16+4]
#define BSTRIDE 136     // Bs [k][128+8]
#define NIT (KK / TBK)  // 32

__global__ __launch_bounds__(256) void gemm_gx_tf32(
    const float* __restrict__ X,   // [B*T, 512]
    const float* __restrict__ W,   // [1024, 3584]
    const float* __restrict__ bias,// [3584]
    float* __restrict__ GX)        // [T][B][3584]
{
    __shared__ float As[3][TBM * ASTRIDE];
    __shared__ float Bs[3][TBK * BSTRIDE];

    const int tid = threadIdx.x;
    const int bm = blockIdx.y * TBM;
    const int bn = blockIdx.x * TBN;
    const int w = tid >> 5, l = tid & 31;
    const int wr = w >> 2, wc = w & 3;
    const int m0w = wr * 64, n0w = wc * 32;
    const int g = l >> 2, tk = l & 3;

    const int arow = tid >> 1;            // 0..127
    const int acol = (tid & 1) * 8;       // 0 or 8
    const int brow = tid >> 4;            // 0..15
    const int bcol = (tid & 15) * 8;      // 0..120

    const float* Ag = X + (long long)(bm + arow) * KK + acol;
    const float* Bg = W + (long long)brow * NG + bn + bcol;

    u32 aDst[3], bDst[3];
#pragma unroll
    for (int s = 0; s < 3; s++) {
        aDst[s] = (u32)__cvta_generic_to_shared(&As[s][arow * ASTRIDE + acol]);
        bDst[s] = (u32)__cvta_generic_to_shared(&Bs[s][brow * BSTRIDE + bcol]);
    }

    float acc[4][4][4];
#pragma unroll
    for (int mi = 0; mi < 4; mi++)
#pragma unroll
        for (int ni = 0; ni < 4; ni++)
#pragma unroll
            for (int q = 0; q < 4; q++) acc[mi][ni][q] = 0.f;

    // prime stages 0 and 1
#pragma unroll
    for (int s = 0; s < 2; s++) {
        const float* An = Ag + s * TBK;
        const float* Bn = Bg + (long long)s * TBK * NG;
        cp16(aDst[s], An);
        cp16(aDst[s] + 16, An + 4);
        cp16(bDst[s], Bn);
        cp16(bDst[s] + 16, Bn + 4);
        asm volatile("cp.async.commit_group;" ::: "memory");
    }

    for (int it = 0; it < NIT; it++) {
        if (it + 1 < NIT) {
            asm volatile("cp.async.wait_group 1;" ::: "memory");
        } else {
            asm volatile("cp.async.wait_group 0;" ::: "memory");
        }
        __syncthreads();   // group 'it' visible; all threads done with buf being refilled

        if (it + 2 < NIT) {
            const int nb = (it + 2) % 3;
            const float* An = Ag + (it + 2) * TBK;
            const float* Bn = Bg + (long long)(it + 2) * TBK * NG;
            cp16(aDst[nb], An);
            cp16(aDst[nb] + 16, An + 4);
            cp16(bDst[nb], Bn);
            cp16(bDst[nb] + 16, Bn + 4);
            asm volatile("cp.async.commit_group;" ::: "memory");
        }

        const int buf = it % 3;
        const float* as = As[buf];
        const float* bs = Bs[buf];
#pragma unroll
        for (int kc = 0; kc < 2; kc++) {
            const int kb = kc * 8;
            u32 af[4][4];
#pragma unroll
            for (int mi = 0; mi < 4; mi++) {
                const float* ap0 = &as[(m0w + mi * 16 + g) * ASTRIDE + kb + tk];
                const float* ap1 = &as[(m0w + mi * 16 + g + 8) * ASTRIDE + kb + tk];
                af[mi][0] = f2tf32(ap0[0]);
                af[mi][1] = f2tf32(ap1[0]);
                af[mi][2] = f2tf32(ap0[4]);
                af[mi][3] = f2tf32(ap1[4]);
            }
            u32 bf[4][2];
#pragma unroll
            for (int ni = 0; ni < 4; ni++) {
                const float* bp = &bs[(kb + tk) * BSTRIDE + n0w + ni * 8 + g];
                bf[ni][0] = f2tf32(bp[0]);
                bf[ni][1] = f2tf32(bp[4 * BSTRIDE]);
            }
#pragma unroll
            for (int mi = 0; mi < 4; mi++)
#pragma unroll
                for (int ni = 0; ni < 4; ni++)
                    mma_tf32(acc[mi][ni][0], acc[mi][ni][1], acc[mi][ni][2], acc[mi][ni][3],
                             af[mi][0], af[mi][1], af[mi][2], af[mi][3],
                             bf[ni][0], bf[ni][1]);
        }
    }

#pragma unroll
    for (int ni = 0; ni < 4; ni++) {
        const int n = bn + n0w + ni * 8 + tk * 2;
        const float2 bv = *(const float2*)&bias[n];
#pragma unroll
        for (int mi = 0; mi < 4; mi++) {
            const int mA = bm + m0w + mi * 16 + g;
            const int mB = mA + 8;
            const int bA = mA >> 8, tA = mA & 255;
            const int bA2 = mB >> 8, tB = mB & 255;
            float2 o0 = make_float2(acc[mi][ni][0] + bv.x, acc[mi][ni][1] + bv.y);
            float2 o1 = make_float2(acc[mi][ni][2] + bv.x, acc[mi][ni][3] + bv.y);
            *(float2*)&GX[((long long)tA * BB + bA) * NG + n] = o0;
            *(float2*)&GX[((long long)tB * BB + bA2) * NG + n] = o1;
        }
    }
}

// ---------------- Phase 2: persistent scan with tf32 mma ----------------
// 128 CTAs = 64 column-groups x 2 batch-halves. The two batch halves are
// fully independent scans -> each syncs only its own 64 CTAs.
#define NBLK 128
#define NBAR 64
#define HROWS 32
#define HS_STRIDE 516
#define WS_U32 (8 * 64 * 64)            // 32768 (8 columns x 16KB)
#define HS_U32 (HROWS * HS_STRIDE)      // 16512
#define GH_STRIDE 66
#define GH_F32 (HROWS * GH_STRIDE)      // 2112
#define SMEM_BYTES ((WS_U32 + HS_U32 + GH_F32) * 4)   // 205568

__device__ __forceinline__ void grid_barrier(u32* cnt, u32* gen_p) {
    __syncthreads();
    if (threadIdx.x == 0) {
        u32 gen;
        asm volatile("ld.relaxed.gpu.u32 %0, [%1];" : "=r"(gen) : "l"(gen_p) : "memory");
        u32 old;
        asm volatile("atom.add.acq_rel.gpu.u32 %0, [%1], 1;" : "=r"(old) : "l"(cnt) : "memory");
        if (old == NBAR - 1) {
            asm volatile("st.relaxed.gpu.u32 [%0], 0;" :: "l"(cnt) : "memory");
            u32 ng = gen + 1;
            asm volatile("st.release.gpu.u32 [%0], %1;" :: "l"(gen_p), "r"(ng) : "memory");
        } else {
            u32 cur;
            do {
                asm volatile("ld.acquire.gpu.u32 %0, [%1];" : "=r"(cur) : "l"(gen_p) : "memory");
            } while (cur == gen);
        }
    }
    __syncthreads();
}

__device__ __forceinline__ float sigmoidf_(float x) {
    return 1.f / (1.f + expf(-x));
}
__device__ __forceinline__ float softplusf_(float x) {
    return fmaxf(x, 0.f) + log1pf(expf(-fabsf(x)));
}

__global__ __launch_bounds__(512, 1) void scan_kernel(
    const float* __restrict__ GX,    // [T][B][3584]
    const float* __restrict__ dtime, // [B,T]
    const float* __restrict__ W,     // [1024, 3584]
    float* out)                      // h_ts[B,T,H] then decay[B,T,4,H]
{
    extern __shared__ u32 smem_u[];
    u32* Ws = smem_u;                       // [8][64][64]
    u32* hs = smem_u + WS_U32;              // [32][516]
    float* gh = (float*)(smem_u + WS_U32 + HS_U32);  // [32][66]

    const int tid = threadIdx.x;
    const int blk = blockIdx.x;
    const int colgrp = blk >> 1;           // 0..63
    const int bh = blk & 1;                // batch half
    const int c0 = colgrp * 8;
    const int bbase = bh * HROWS;

    u32* bar_cnt = &g_bar_count[bh * 32];
    u32* bar_gen = &g_bar_gen[bh * 32];

    const int w = tid >> 5;
    const int l = tid & 31;
    const int mt = w & 1;
    const int nt = w >> 1;                 // 0..7 column within the 8
    const int m0 = mt * 16;
    const int g = l >> 2;
    const int tk = l & 3;

    const int r = tid & 255;
    const int b2 = r >> 3;                 // 0..31 local batch row
    const int cc = r & 7;                  // 0..7
    const int b = bbase + b2;
    const int c = c0 + cc;

    // one-time init: W_h fragments (tf32, lane order) for 8 columns
    for (int i = tid; i < WS_U32; i += 512) {
        int slot = i & 1;
        int l2 = (i >> 1) & 31;
        int ks = (i >> 6) & 63;
        int nt2 = i >> 12;                 // 0..7
        int k = ks * 8 + (l2 & 3) + slot * 4;
        int j = l2 >> 2;
        float v = 0.f;
        if (j < 7) v = W[(long long)(KK + k) * NG + j * HH + c0 + nt2];
        Ws[i] = f2tf32(v);
    }
    for (int i = tid; i < GH_F32; i += 512) gh[i] = 0.f;
    __syncthreads();

    float cf_r = 0.f;
    float cb_r = 0.f;

    const u32 hA_lm = (u32)__cvta_generic_to_shared(
        hs + (m0 + (l & 15)) * HS_STRIDE + ((l >> 4) & 1) * 4);
    const u32* wB  = Ws + nt * 4096 + l * 2;
    const long long DEC0 = (long long)BB * TT * HH;

    // prefetch step-0 gate inputs
    float x0, x1, x2, x3, x4, x5, x6, dt;
    if (tid < 256) {
        const float* gx = GX + (long long)b * NG + c;
        x0 = gx[0 * HH];
        x1 = gx[1 * HH];
        x2 = gx[2 * HH];
        x3 = gx[3 * HH];
        x4 = gx[4 * HH];
        x5 = gx[5 * HH];
        x6 = gx[6 * HH];
        dt = dtime[b * TT];
    }

    for (int t = 0; t < TT; t++) {
        if (t > 0) {
            // stage this CTA's 32 batch rows of h_{t-1} -> SMEM (tf32)
#pragma unroll
            for (int i = 0; i < 8; i++) {
                int lin = i * 512 + tid;
                int bb = lin >> 7;
                int q = lin & 127;
                float4 v = *(const float4*)&out[((long long)(bbase + bb) * TT + (t - 1)) * HH + q * 4];
                uint4 u;
                u.x = f2tf32(v.x);
                u.y = f2tf32(v.y);
                u.z = f2tf32(v.z);
                u.w = f2tf32(v.w);
                *(uint4*)&hs[bb * HS_STRIDE + q * 4] = u;
            }
            __syncthreads();

            float pa0 = 0.f, pa1 = 0.f, pa2 = 0.f, pa3 = 0.f;
            float pb0 = 0.f, pb1 = 0.f, pb2 = 0.f, pb3 = 0.f;
#pragma unroll 4
            for (int ks = 0; ks < 64; ks += 2) {
                u32 a0, a1, a2, a3;
                asm volatile(
                    "ldmatrix.sync.aligned.m8n8.x4.shared.b16 {%0,%1,%2,%3}, [%4];"
                    : "=r"(a0), "=r"(a1), "=r"(a2), "=r"(a3)
                    : "r"(hA_lm + ks * 32));
                uint2 bfr = *(const uint2*)(wB + ks * 64);
                mma_tf32(pa0, pa1, pa2, pa3, a0, a1, a2, a3, bfr.x, bfr.y);

                u32 e0, e1, e2, e3;
                asm volatile(
                    "ldmatrix.sync.aligned.m8n8.x4.shared.b16 {%0,%1,%2,%3}, [%4];"
                    : "=r"(e0), "=r"(e1), "=r"(e2), "=r"(e3)
                    : "r"(hA_lm + (ks + 1) * 32));
                uint2 bf2 = *(const uint2*)(wB + (ks + 1) * 64);
                mma_tf32(pb0, pb1, pb2, pb3, e0, e1, e2, e3, bf2.x, bf2.y);
            }
            const float acc0 = pa0 + pb0;
            const float acc1 = pa1 + pb1;
            const float acc2 = pa2 + pb2;
            const float acc3 = pa3 + pb3;

            const int col = nt * 8 + tk * 2;
            *(float2*)&gh[(m0 + g) * GH_STRIDE + col] = make_float2(acc0, acc1);
            *(float2*)&gh[(m0 + g + 8) * GH_STRIDE + col] = make_float2(acc2, acc3);
            __syncthreads();
        }

        if (tid < 256) {
            const float* ghr = &gh[b2 * GH_STRIDE + cc * 8];
            const float g0 = x0 + ghr[0];
            const float g1 = x1 + ghr[1];
            const float g2 = x2 + ghr[2];
            const float g3 = x3 + ghr[3];
            const float g4 = x4 + ghr[4];
            const float g5 = x5 + ghr[5];
            const float g6 = x6 + ghr[6];

            const float gate_i  = sigmoidf_(g0);
            const float gate_f  = sigmoidf_(g1);
            const float gate_o  = sigmoidf_(g2);
            const float gate_ib = sigmoidf_(g3);
            const float gate_fb = sigmoidf_(g4);
            const float gate_d  = softplusf_(g5);
            const float z       = tanhf(g6);

            const float c_t  = gate_f  * cf_r + gate_i  * z;
            const float cb_t = gate_fb * cb_r + gate_ib * z;
            const float cfn  = cb_t + (c_t - cb_t) * expf(-gate_d * dt);
            const float h_t  = gate_o * tanhf(cfn);

            cf_r = cfn;
            cb_r = cb_t;

            out[((long long)b * TT + t) * HH + c] = h_t;
            float* dec = out + DEC0 + ((long long)(b * TT + t) * 4) * HH + c;
            dec[0 * HH] = c_t;
            dec[1 * HH] = cb_t;
            dec[2 * HH] = gate_d;
            dec[3 * HH] = gate_o;

            if (t + 1 < TT) {
                const float* gx = GX + ((long long)(t + 1) * BB + b) * NG + c;
                x0 = gx[0 * HH];
                x1 = gx[1 * HH];
                x2 = gx[2 * HH];
                x3 = gx[3 * HH];
                x4 = gx[4 * HH];
                x5 = gx[5 * HH];
                x6 = gx[6 * HH];
                dt = dtime[b * TT + t + 1];
            }
        }

        if (t + 1 < TT) grid_barrier(bar_cnt, bar_gen);
    }
}

// ---------------- launch ----------------
extern "C" void kernel_launch(void* const* d_in, const int* in_sizes, int n_in,
                              void* d_out, int out_size) {
    (void)in_sizes; (void)n_in; (void)out_size;
    const float* X     = (const float*)d_in[0];  // seq_type_embed [B,T,H]
    const float* dtime = (const float*)d_in[1];  // [B,T]
    const float* W     = (const float*)d_in[2];  // [2H, 7H]
    const float* bias  = (const float*)d_in[3];  // [7H]
    float* out = (float*)d_out;

    float* GX;
    cudaGetSymbolAddress((void**)&GX, g_gx);

    // Phase 1: tf32 mma GEMM for x-part pre-activations (3-stage cp.async)
    dim3 grid1(NG / TBN, (BB * TT) / TBM);   // (28, 128)
    gemm_gx_tf32<<<grid1, 256>>>(X, W, bias, GX);

    // Phase 2: one persistent kernel for the whole scan
    cudaFuncSetAttribute(scan_kernel, cudaFuncAttributeMaxDynamicSharedMemorySize,
                         SMEM_BYTES);
    scan_kernel<<<NBLK, 512, SMEM_BYTES>>>(GX, dtime, W, out);
}

// round 16
// speedup vs baseline: 1.4738x; 1.0111x over previous
#include <cuda_runtime.h>
#include <math.h>

// Problem constants
#define BB 64      // batch
#define TT 256     // time steps
#define HH 512     // hidden
#define NG 3584    // 7*H gate width
#define KK 512     // per-half K (x part / h part each 512)

typedef unsigned long long u64;
typedef unsigned int u32;

// ---------------- tf32 mma helpers ----------------
__device__ __forceinline__ u32 f2tf32(float f) {
    u32 u; asm("cvt.rna.tf32.f32 %0, %1;" : "=r"(u) : "f"(f)); return u;
}
__device__ __forceinline__ void mma_tf32(float &c0, float &c1, float &c2, float &c3,
                                         u32 a0, u32 a1, u32 a2, u32 a3,
                                         u32 b0, u32 b1) {
    asm("mma.sync.aligned.m16n8k8.row.col.f32.tf32.tf32.f32 "
        "{%0,%1,%2,%3},{%4,%5,%6,%7},{%8,%9},{%0,%1,%2,%3};"
        : "+f"(c0), "+f"(c1), "+f"(c2), "+f"(c3)
        : "r"(a0), "r"(a1), "r"(a2), "r"(a3), "r"(b0), "r"(b1));
}
__device__ __forceinline__ void cp16(u32 dst_smem, const void* src) {
    asm volatile("cp.async.ca.shared.global [%0], [%1], 16;"
                 :: "r"(dst_smem), "l"(src) : "memory");
}

// ---------------- scratch (no allocations allowed) ----------------
// GX layout: [t][b][n], n = j*512 + c  (x-part pre-activations + bias)
__device__ float g_gx[(long long)BB * TT * NG];   // ~224MB
__device__ u32 g_xt[(long long)BB * TT * KK];     // X pre-converted to tf32 (32MB)
__device__ u32 g_wt[(long long)KK * NG];          // W x-half pre-converted (7MB)
// two independent 64-CTA barriers (one per batch half), separate lines
__device__ u32 g_bar_count[64];   // [0] and [32] used
__device__ u32 g_bar_gen[64];     // [0] and [32] used

// ---------------- Phase 0: convert fp32 -> tf32 (once) ----------------
__global__ __launch_bounds__(256) void cvt_tf32_kernel(
    const float4* __restrict__ src, uint4* __restrict__ dst, int n4)
{
    int i = blockIdx.x * 256 + threadIdx.x;
    if (i < n4) {
        float4 v = src[i];
        uint4 u;
        u.x = f2tf32(v.x);
        u.y = f2tf32(v.y);
        u.z = f2tf32(v.z);
        u.w = f2tf32(v.w);
        dst[i] = u;
    }
}

// ---------------- Phase 1: GX = Xt @ Wt + b, tf32 mma, pre-converted -------
// 3-stage cp.async ring; A-fragments via ldmatrix.x4 (lane recipe validated
// in the scan kernel); B-fragments via conflict-free scalar LDS (bank=tk*8+g).
#define TBM 128
#define TBN 128
#define TBK 16
#define ASTRIDE 20      // As [m][16+4] u32; row = 80B (16B-aligned for ldmatrix)
#define BSTRIDE 136     // Bs [k][128+8] u32
#define NIT (KK / TBK)  // 32

__global__ __launch_bounds__(256) void gemm_gx_tf32(
    const u32* __restrict__ Xt,    // [B*T, 512] tf32
    const u32* __restrict__ Wt,    // [512, 3584] tf32 (x-half of W)
    const float* __restrict__ bias,// [3584]
    float* __restrict__ GX)        // [T][B][3584]
{
    __shared__ u32 As[3][TBM * ASTRIDE];
    __shared__ u32 Bs[3][TBK * BSTRIDE];

    const int tid = threadIdx.x;
    const int bm = blockIdx.y * TBM;
    const int bn = blockIdx.x * TBN;
    const int w = tid >> 5, l = tid & 31;
    const int wr = w >> 2, wc = w & 3;
    const int m0w = wr * 64, n0w = wc * 32;
    const int g = l >> 2, tk = l & 3;

    const int arow = tid >> 1;            // 0..127
    const int acol = (tid & 1) * 8;       // 0 or 8
    const int brow = tid >> 4;            // 0..15
    const int bcol = (tid & 15) * 8;      // 0..120

    const u32* Ag = Xt + (long long)(bm + arow) * KK + acol;
    const u32* Bg = Wt + (long long)brow * NG + bn + bcol;

    u32 aDst[3], bDst[3], lmA[3];
#pragma unroll
    for (int s = 0; s < 3; s++) {
        aDst[s] = (u32)__cvta_generic_to_shared(&As[s][arow * ASTRIDE + acol]);
        bDst[s] = (u32)__cvta_generic_to_shared(&Bs[s][brow * BSTRIDE + bcol]);
        // ldmatrix base: row = m0w + (l&15), col offset (l>>4)*4 u32
        lmA[s] = (u32)__cvta_generic_to_shared(
            &As[s][(m0w + (l & 15)) * ASTRIDE + ((l >> 4) & 1) * 4]);
    }

    float acc[4][4][4];
#pragma unroll
    for (int mi = 0; mi < 4; mi++)
#pragma unroll
        for (int ni = 0; ni < 4; ni++)
#pragma unroll
            for (int q = 0; q < 4; q++) acc[mi][ni][q] = 0.f;

    // prime stages 0 and 1
#pragma unroll
    for (int s = 0; s < 2; s++) {
        const u32* An = Ag + s * TBK;
        const u32* Bn = Bg + (long long)s * TBK * NG;
        cp16(aDst[s], An);
        cp16(aDst[s] + 16, An + 4);
        cp16(bDst[s], Bn);
        cp16(bDst[s] + 16, Bn + 4);
        asm volatile("cp.async.commit_group;" ::: "memory");
    }

    for (int it = 0; it < NIT; it++) {
        if (it + 1 < NIT) {
            asm volatile("cp.async.wait_group 1;" ::: "memory");
        } else {
            asm volatile("cp.async.wait_group 0;" ::: "memory");
        }
        __syncthreads();

        if (it + 2 < NIT) {
            const int nb = (it + 2) % 3;
            const u32* An = Ag + (it + 2) * TBK;
            const u32* Bn = Bg + (long long)(it + 2) * TBK * NG;
            cp16(aDst[nb], An);
            cp16(aDst[nb] + 16, An + 4);
            cp16(bDst[nb], Bn);
            cp16(bDst[nb] + 16, Bn + 4);
            asm volatile("cp.async.commit_group;" ::: "memory");
        }

        const int buf = it % 3;
        const u32* bs = Bs[buf];
        const u32 lma = lmA[buf];
#pragma unroll
        for (int kc = 0; kc < 2; kc++) {
            const int kb = kc * 8;
            u32 af[4][4];
#pragma unroll
            for (int mi = 0; mi < 4; mi++) {
                asm volatile(
                    "ldmatrix.sync.aligned.m8n8.x4.shared.b16 {%0,%1,%2,%3}, [%4];"
                    : "=r"(af[mi][0]), "=r"(af[mi][1]), "=r"(af[mi][2]), "=r"(af[mi][3])
                    : "r"(lma + (u32)((mi * 16 * ASTRIDE + kb) * 4)));
            }
            u32 bf[4][2];
#pragma unroll
            for (int ni = 0; ni < 4; ni++) {
                const u32* bp = &bs[(kb + tk) * BSTRIDE + n0w + ni * 8 + g];
                bf[ni][0] = bp[0];
                bf[ni][1] = bp[4 * BSTRIDE];
            }
#pragma unroll
            for (int mi = 0; mi < 4; mi++)
#pragma unroll
                for (int ni = 0; ni < 4; ni++)
                    mma_tf32(acc[mi][ni][0], acc[mi][ni][1], acc[mi][ni][2], acc[mi][ni][3],
                             af[mi][0], af[mi][1], af[mi][2], af[mi][3],
                             bf[ni][0], bf[ni][1]);
        }
    }

#pragma unroll
    for (int ni = 0; ni < 4; ni++) {
        const int n = bn + n0w + ni * 8 + tk * 2;
        const float2 bv = *(const float2*)&bias[n];
#pragma unroll
        for (int mi = 0; mi < 4; mi++) {
            const int mA = bm + m0w + mi * 16 + g;
            const int mB = mA + 8;
            const int bA = mA >> 8, tA = mA & 255;
            const int bA2 = mB >> 8, tB = mB & 255;
            float2 o0 = make_float2(acc[mi][ni][0] + bv.x, acc[mi][ni][1] + bv.y);
            float2 o1 = make_float2(acc[mi][ni][2] + bv.x, acc[mi][ni][3] + bv.y);
            *(float2*)&GX[((long long)tA * BB + bA) * NG + n] = o0;
            *(float2*)&GX[((long long)tB * BB + bA2) * NG + n] = o1;
        }
    }
}

// ---------------- Phase 2: persistent scan (UNCHANGED from 2431us config) --
#define NBLK 128
#define NBAR 64
#define HROWS 32
#define HS_STRIDE 516
#define WS_U32 (8 * 64 * 64)            // 32768 (8 columns x 16KB)
#define HS_U32 (HROWS * HS_STRIDE)      // 16512
#define GH_STRIDE 66
#define GH_F32 (HROWS * GH_STRIDE)      // 2112
#define SMEM_BYTES ((WS_U32 + HS_U32 + GH_F32) * 4)   // 205568

__device__ __forceinline__ void grid_barrier(u32* cnt, u32* gen_p) {
    __syncthreads();
    if (threadIdx.x == 0) {
        u32 gen;
        asm volatile("ld.relaxed.gpu.u32 %0, [%1];" : "=r"(gen) : "l"(gen_p) : "memory");
        u32 old;
        asm volatile("atom.add.acq_rel.gpu.u32 %0, [%1], 1;" : "=r"(old) : "l"(cnt) : "memory");
        if (old == NBAR - 1) {
            asm volatile("st.relaxed.gpu.u32 [%0], 0;" :: "l"(cnt) : "memory");
            u32 ng = gen + 1;
            asm volatile("st.release.gpu.u32 [%0], %1;" :: "l"(gen_p), "r"(ng) : "memory");
        } else {
            u32 cur;
            do {
                asm volatile("ld.acquire.gpu.u32 %0, [%1];" : "=r"(cur) : "l"(gen_p) : "memory");
            } while (cur == gen);
        }
    }
    __syncthreads();
}

__device__ __forceinline__ float sigmoidf_(float x) {
    return 1.f / (1.f + expf(-x));
}
__device__ __forceinline__ float softplusf_(float x) {
    return fmaxf(x, 0.f) + log1pf(expf(-fabsf(x)));
}

__global__ __launch_bounds__(512, 1) void scan_kernel(
    const float* __restrict__ GX,    // [T][B][3584]
    const float* __restrict__ dtime, // [B,T]
    const float* __restrict__ W,     // [1024, 3584]
    float* out)                      // h_ts[B,T,H] then decay[B,T,4,H]
{
    extern __shared__ u32 smem_u[];
    u32* Ws = smem_u;                       // [8][64][64]
    u32* hs = smem_u + WS_U32;              // [32][516]
    float* gh = (float*)(smem_u + WS_U32 + HS_U32);  // [32][66]

    const int tid = threadIdx.x;
    const int blk = blockIdx.x;
    const int colgrp = blk >> 1;           // 0..63
    const int bh = blk & 1;                // batch half
    const int c0 = colgrp * 8;
    const int bbase = bh * HROWS;

    u32* bar_cnt = &g_bar_count[bh * 32];
    u32* bar_gen = &g_bar_gen[bh * 32];

    const int w = tid >> 5;
    const int l = tid & 31;
    const int mt = w & 1;
    const int nt = w >> 1;                 // 0..7 column within the 8
    const int m0 = mt * 16;
    const int g = l >> 2;
    const int tk = l & 3;

    const int r = tid & 255;
    const int b2 = r >> 3;                 // 0..31 local batch row
    const int cc = r & 7;                  // 0..7
    const int b = bbase + b2;
    const int c = c0 + cc;

    // one-time init: W_h fragments (tf32, lane order) for 8 columns
    for (int i = tid; i < WS_U32; i += 512) {
        int slot = i & 1;
        int l2 = (i >> 1) & 31;
        int ks = (i >> 6) & 63;
        int nt2 = i >> 12;                 // 0..7
        int k = ks * 8 + (l2 & 3) + slot * 4;
        int j = l2 >> 2;
        float v = 0.f;
        if (j < 7) v = W[(long long)(KK + k) * NG + j * HH + c0 + nt2];
        Ws[i] = f2tf32(v);
    }
    for (int i = tid; i < GH_F32; i += 512) gh[i] = 0.f;
    __syncthreads();

    float cf_r = 0.f;
    float cb_r = 0.f;

    const u32 hA_lm = (u32)__cvta_generic_to_shared(
        hs + (m0 + (l & 15)) * HS_STRIDE + ((l >> 4) & 1) * 4);
    const u32* wB  = Ws + nt * 4096 + l * 2;
    const long long DEC0 = (long long)BB * TT * HH;

    // prefetch step-0 gate inputs
    float x0, x1, x2, x3, x4, x5, x6, dt;
    if (tid < 256) {
        const float* gx = GX + (long long)b * NG + c;
        x0 = gx[0 * HH];
        x1 = gx[1 * HH];
        x2 = gx[2 * HH];
        x3 = gx[3 * HH];
        x4 = gx[4 * HH];
        x5 = gx[5 * HH];
        x6 = gx[6 * HH];
        dt = dtime[b * TT];
    }

    for (int t = 0; t < TT; t++) {
        if (t > 0) {
            // stage this CTA's 32 batch rows of h_{t-1} -> SMEM (tf32)
#pragma unroll
            for (int i = 0; i < 8; i++) {
                int lin = i * 512 + tid;
                int bb = lin >> 7;
                int q = lin & 127;
                float4 v = *(const float4*)&out[((long long)(bbase + bb) * TT + (t - 1)) * HH + q * 4];
                uint4 u;
                u.x = f2tf32(v.x);
                u.y = f2tf32(v.y);
                u.z = f2tf32(v.z);
                u.w = f2tf32(v.w);
                *(uint4*)&hs[bb * HS_STRIDE + q * 4] = u;
            }
            __syncthreads();

            float pa0 = 0.f, pa1 = 0.f, pa2 = 0.f, pa3 = 0.f;
            float pb0 = 0.f, pb1 = 0.f, pb2 = 0.f, pb3 = 0.f;
#pragma unroll 4
            for (int ks = 0; ks < 64; ks += 2) {
                u32 a0, a1, a2, a3;
                asm volatile(
                    "ldmatrix.sync.aligned.m8n8.x4.shared.b16 {%0,%1,%2,%3}, [%4];"
                    : "=r"(a0), "=r"(a1), "=r"(a2), "=r"(a3)
                    : "r"(hA_lm + ks * 32));
                uint2 bfr = *(const uint2*)(wB + ks * 64);
                mma_tf32(pa0, pa1, pa2, pa3, a0, a1, a2, a3, bfr.x, bfr.y);

                u32 e0, e1, e2, e3;
                asm volatile(
                    "ldmatrix.sync.aligned.m8n8.x4.shared.b16 {%0,%1,%2,%3}, [%4];"
                    : "=r"(e0), "=r"(e1), "=r"(e2), "=r"(e3)
                    : "r"(hA_lm + (ks + 1) * 32));
                uint2 bf2 = *(const uint2*)(wB + (ks + 1) * 64);
                mma_tf32(pb0, pb1, pb2, pb3, e0, e1, e2, e3, bf2.x, bf2.y);
            }
            const float acc0 = pa0 + pb0;
            const float acc1 = pa1 + pb1;
            const float acc2 = pa2 + pb2;
            const float acc3 = pa3 + pb3;

            const int col = nt * 8 + tk * 2;
            *(float2*)&gh[(m0 + g) * GH_STRIDE + col] = make_float2(acc0, acc1);
            *(float2*)&gh[(m0 + g + 8) * GH_STRIDE + col] = make_float2(acc2, acc3);
            __syncthreads();
        }

        if (tid < 256) {
            const float* ghr = &gh[b2 * GH_STRIDE + cc * 8];
            const float g0 = x0 + ghr[0];
            const float g1 = x1 + ghr[1];
            const float g2 = x2 + ghr[2];
            const float g3 = x3 + ghr[3];
            const float g4 = x4 + ghr[4];
            const float g5 = x5 + ghr[5];
            const float g6 = x6 + ghr[6];

            const float gate_i  = sigmoidf_(g0);
            const float gate_f  = sigmoidf_(g1);
            const float gate_o  = sigmoidf_(g2);
            const float gate_ib = sigmoidf_(g3);
            const float gate_fb = sigmoidf_(g4);
            const float gate_d  = softplusf_(g5);
            const float z       = tanhf(g6);

            const float c_t  = gate_f  * cf_r + gate_i  * z;
            const float cb_t = gate_fb * cb_r + gate_ib * z;
            const float cfn  = cb_t + (c_t - cb_t) * expf(-gate_d * dt);
            const float h_t  = gate_o * tanhf(cfn);

            cf_r = cfn;
            cb_r = cb_t;

            out[((long long)b * TT + t) * HH + c] = h_t;
            float* dec = out + DEC0 + ((long long)(b * TT + t) * 4) * HH + c;
            dec[0 * HH] = c_t;
            dec[1 * HH] = cb_t;
            dec[2 * HH] = gate_d;
            dec[3 * HH] = gate_o;

            if (t + 1 < TT) {
                const float* gx = GX + ((long long)(t + 1) * BB + b) * NG + c;
                x0 = gx[0 * HH];
                x1 = gx[1 * HH];
                x2 = gx[2 * HH];
                x3 = gx[3 * HH];
                x4 = gx[4 * HH];
                x5 = gx[5 * HH];
                x6 = gx[6 * HH];
                dt = dtime[b * TT + t + 1];
            }
        }

        if (t + 1 < TT) grid_barrier(bar_cnt, bar_gen);
    }
}

// ---------------- launch ----------------
extern "C" void kernel_launch(void* const* d_in, const int* in_sizes, int n_in,
                              void* d_out, int out_size) {
    (void)in_sizes; (void)n_in; (void)out_size;
    const float* X     = (const float*)d_in[0];  // seq_type_embed [B,T,H]
    const float* dtime = (const float*)d_in[1];  // [B,T]
    const float* W     = (const float*)d_in[2];  // [2H, 7H]
    const float* bias  = (const float*)d_in[3];  // [7H]
    float* out = (float*)d_out;

    float* GX;
    u32 *Xt, *Wt;
    cudaGetSymbolAddress((void**)&GX, g_gx);
    cudaGetSymbolAddress((void**)&Xt, g_xt);
    cudaGetSymbolAddress((void**)&Wt, g_wt);

    // Phase 0: one-time tf32 pre-conversion of X and W's x-half
    {
        const int nx4 = (BB * TT * KK) / 4;          // 2,097,152
        const int nw4 = (KK * NG) / 4;               // 458,752
        cvt_tf32_kernel<<<(nx4 + 255) / 256, 256>>>((const float4*)X, (uint4*)Xt, nx4);
        cvt_tf32_kernel<<<(nw4 + 255) / 256, 256>>>((const float4*)W, (uint4*)Wt, nw4);
    }

    // Phase 1: tf32 mma GEMM on pre-converted data
    dim3 grid1(NG / TBN, (BB * TT) / TBM);   // (28, 128)
    gemm_gx_tf32<<<grid1, 256>>>(Xt, Wt, bias, GX);

    // Phase 2: one persistent kernel for the whole scan
    cudaFuncSetAttribute(scan_kernel, cudaFuncAttributeMaxDynamicSharedMemorySize,
                         SMEM_BYTES);
    scan_kernel<<<NBLK, 512, SMEM_BYTES>>>(GX, dtime, W, out);
}